// round 8
// baseline (speedup 1.0000x reference)
#include <cuda_runtime.h>
#include <cuda_fp16.h>
#include <math.h>

#define B_   16
#define C_   256
#define NH_  8
#define HD_  32
#define N_   1024
#define M_   256
#define HID_ 24
#define EPS_ 1e-5f

// ---------------- scratch ----------------
__device__ float  S_q[B_ * NH_ * N_ * HD_];
__device__ float  S_k[B_ * NH_ * M_ * HD_];
__device__ float  S_v[B_ * NH_ * M_ * HD_];
__device__ __half S_attn[B_ * NH_ * N_ * M_];   // 67 MB
__device__ __half S_y[B_ * HID_ * N_ * M_];     // 202 MB
__device__ float  S_r[B_ * NH_ * N_ * M_];      // 134 MB fp32 (accuracy)
__device__ float  S_hout[B_ * N_ * C_];
__device__ float  S_gram[B_ * 36];
__device__ float  S_stats1[B_ * 3 * 2];
__device__ float  S_stats2[B_ * 3 * 2];
__device__ float  S_stats3[B_ * 2];

__device__ __forceinline__ float wred(float v) {
#pragma unroll
    for (int o = 16; o; o >>= 1) v += __shfl_xor_sync(0xffffffffu, v, o);
    return v;
}
__device__ __forceinline__ float tanh_fast(float x) {
    float y;
    asm("tanh.approx.f32 %0, %1;" : "=f"(y) : "f"(x));
    return y;
}
__device__ __forceinline__ float fswish(float x) {
    return 0.5f * x * (1.f + tanh_fast(0.5f * x));
}

// ---------------- fused projections (q + kv) + scratch zeroing ----------------
__global__ __launch_bounds__(256) void k_all_proj(
    const float* __restrict__ q, const float* __restrict__ Wq,
    const float* __restrict__ kv, const float* __restrict__ Wkv) {
    __shared__ float sbuf[8192];
    const int b = blockIdx.x;
    const int y = blockIdx.y;
    const int t = threadIdx.x;
    if (b == 0 && y == 0) {
        for (int i = t; i < 576; i += 256) S_gram[i] = 0.f;
        if (t < 96) S_stats2[t] = 0.f;
        if (t < 32) S_stats3[t] = 0.f;
    }
    if (y < 32) {
        const int n0 = y * 32;
        for (int idx = t; idx < 2048; idx += 256) {
            int c = idx >> 3, i4 = idx & 7;
            ((float4*)sbuf)[idx] = ((const float4*)(q + (b * 256 + c) * 1024 + n0))[i4];
        }
        __syncthreads();
        float acc[32];
#pragma unroll
        for (int i = 0; i < 32; i++) acc[i] = 0.f;
        const float* wrow = Wq + t * 256;
        for (int c = 0; c < 256; c++) {
            float w = __ldg(wrow + c);
            const float4* q4 = (const float4*)(sbuf + c * 32);
#pragma unroll
            for (int i4 = 0; i4 < 8; i4++) {
                float4 qq = q4[i4];
                acc[i4 * 4 + 0] += qq.x * w;
                acc[i4 * 4 + 1] += qq.y * w;
                acc[i4 * 4 + 2] += qq.z * w;
                acc[i4 * 4 + 3] += qq.w * w;
            }
        }
        int h = t >> 5, d = t & 31;
#pragma unroll
        for (int i = 0; i < 32; i++)
            S_q[((b * 8 + h) * 1024 + n0 + i) * 32 + d] = acc[i];
    } else {
        const int m0 = (y - 32) * 16;
        for (int idx = t; idx < 4096; idx += 256) {
            int c = idx >> 4, i = idx & 15;
            sbuf[c * 16 + i] = kv[(b * 256 + c) * 256 + m0 + i];
        }
        __syncthreads();
        for (int jj = 0; jj < 2; jj++) {
            int j = t + jj * 256;
            float acc[16];
#pragma unroll
            for (int i = 0; i < 16; i++) acc[i] = 0.f;
            const float* wrow = Wkv + j * 256;
            for (int c = 0; c < 256; c++) {
                float w = __ldg(wrow + c);
                const float4* k4 = (const float4*)(sbuf + c * 16);
#pragma unroll
                for (int i4 = 0; i4 < 4; i4++) {
                    float4 kk = k4[i4];
                    acc[i4 * 4 + 0] += kk.x * w;
                    acc[i4 * 4 + 1] += kk.y * w;
                    acc[i4 * 4 + 2] += kk.z * w;
                    acc[i4 * 4 + 3] += kk.w * w;
                }
            }
            float* dst = (j < 256) ? S_k : S_v;
            int hd = j & 255;
            int h = hd >> 5, d = hd & 31;
#pragma unroll
            for (int i = 0; i < 16; i++)
                dst[((b * 8 + h) * 256 + m0 + i) * 32 + d] = acc[i];
        }
    }
}

// ---------------- attention: register-tiled QK^T + softmax -> half ----------------
__global__ __launch_bounds__(256) void k_attn(const float* __restrict__ rpb) {
    const int bh = blockIdx.x;
    const int n0 = blockIdx.y * 64;
    __shared__ float Qs[32 * 68];
    __shared__ float Ks[32 * 260];
    const int t = threadIdx.x;
    {
        const int d = t & 31, g = t >> 5;
        const float* qsrc = S_q + (size_t)(bh * 1024 + n0) * 32 + d;
#pragma unroll
        for (int i = 0; i < 8; i++)
            Qs[d * 68 + g * 8 + i] = qsrc[(g * 8 + i) * 32];
        const float* ksrc = S_k + (size_t)bh * 8192 + d;
#pragma unroll
        for (int i = 0; i < 32; i++)
            Ks[d * 260 + g * 32 + i] = ksrc[(g * 32 + i) * 32];
    }
    __syncthreads();
    const int mg = t & 31;
    const int ng = t >> 5;
    float acc[8][8];
#pragma unroll
    for (int i = 0; i < 8; i++)
#pragma unroll
        for (int j = 0; j < 8; j++) acc[i][j] = 0.f;
#pragma unroll 4
    for (int k = 0; k < 32; k++) {
        float4 q0 = *(const float4*)&Qs[k * 68 + ng * 8];
        float4 q1 = *(const float4*)&Qs[k * 68 + ng * 8 + 4];
        float4 k0 = *(const float4*)&Ks[k * 260 + mg * 8];
        float4 k1 = *(const float4*)&Ks[k * 260 + mg * 8 + 4];
        float qv[8] = {q0.x, q0.y, q0.z, q0.w, q1.x, q1.y, q1.z, q1.w};
        float kw[8] = {k0.x, k0.y, k0.z, k0.w, k1.x, k1.y, k1.z, k1.w};
#pragma unroll
        for (int i = 0; i < 8; i++)
#pragma unroll
            for (int j = 0; j < 8; j++) acc[i][j] += qv[i] * kw[j];
    }
    const float scale = 0.17677669529663689f;
#pragma unroll
    for (int i = 0; i < 8; i++) {
        const int n = n0 + ng * 8 + i;
        const float* rp = rpb + (size_t)n * 256 + mg * 8;
        float4 r0 = *(const float4*)rp;
        float4 r1 = *(const float4*)(rp + 4);
        float rb[8] = {r0.x, r0.y, r0.z, r0.w, r1.x, r1.y, r1.z, r1.w};
        float mx = -1e30f;
#pragma unroll
        for (int j = 0; j < 8; j++) {
            acc[i][j] = acc[i][j] * scale + rb[j];
            mx = fmaxf(mx, acc[i][j]);
        }
#pragma unroll
        for (int o = 16; o; o >>= 1) mx = fmaxf(mx, __shfl_xor_sync(0xffffffffu, mx, o));
        float s = 0.f;
#pragma unroll
        for (int j = 0; j < 8; j++) {
            float e = __expf(acc[i][j] - mx);
            acc[i][j] = e;
            s += e;
        }
        s = wred(s);
        float inv = __fdividef(1.f, s);
        union { uint4 u4; __half2 h2[4]; } pk;
#pragma unroll
        for (int j = 0; j < 4; j++)
            pk.h2[j] = __floats2half2_rn(acc[i][2 * j] * inv, acc[i][2 * j + 1] * inv);
        *(uint4*)(S_attn + (size_t)(bh * 1024 + n) * 256 + mg * 8) = pk.u4;
    }
}

// ---------------- head Gram matrix (half2 reads) ----------------
__global__ __launch_bounds__(256) void k_gram() {
    const int b = blockIdx.x;
    const int base2 = blockIdx.y * 4096;
    __shared__ float gs[36];
    const int t = threadIdx.x;
    if (t < 36) gs[t] = 0.f;
    __syncthreads();
    float g[36];
#pragma unroll
    for (int c = 0; c < 36; c++) g[c] = 0.f;
    const __half2* A = (const __half2*)S_attn + (size_t)b * 1048576;
#pragma unroll 1
    for (int k = 0; k < 16; k++) {
        int p = base2 + k * 256 + t;
        float2 a[8];
#pragma unroll
        for (int h = 0; h < 8; h++) a[h] = __half22float2(A[h * 131072 + p]);
        int c = 0;
#pragma unroll
        for (int i = 0; i < 8; i++)
#pragma unroll
            for (int j = i; j < 8; j++) {
                g[c] += a[i].x * a[j].x + a[i].y * a[j].y;
                c++;
            }
    }
#pragma unroll
    for (int c = 0; c < 36; c++) {
        g[c] = wred(g[c]);
        if ((t & 31) == 0) atomicAdd(&gs[c], g[c]);
    }
    __syncthreads();
    if (t < 36) atomicAdd(&S_gram[b * 36 + t], gs[t]);
}

// ---------------- derive GN1 stats analytically ----------------
__global__ void k_stats1p(const float* __restrict__ W_exp) {
    const int t = threadIdx.x;
    if (t >= 48) return;
    const int b = t / 3, g = t % 3;
    float sumw = 0.f, sumxx = 0.f;
    const float* G = S_gram + b * 36;
    for (int o = g * 8; o < g * 8 + 8; o++) {
        float wo[8];
#pragma unroll
        for (int h = 0; h < 8; h++) wo[h] = W_exp[o * 8 + h];
#pragma unroll
        for (int h = 0; h < 8; h++) sumw += wo[h];
#pragma unroll
        for (int i = 0; i < 8; i++)
#pragma unroll
            for (int j = 0; j < 8; j++) {
                int a = i < j ? i : j, bb = i < j ? j : i;
                sumxx += wo[i] * wo[j] * G[8 * a - a * (a - 1) / 2 + (bb - a)];
            }
    }
    S_stats1[b * 6 + 2 * g] = sumw * 1024.f;
    S_stats1[b * 6 + 2 * g + 1] = sumxx;
}

// ---------------- DLA pass 0 ----------------
__global__ __launch_bounds__(256, 3) void k_dla0(
    const float* __restrict__ W_exp, const float* __restrict__ g1,
    const float* __restrict__ b1, const float* __restrict__ W_dw) {
    const int m0 = blockIdx.x * 32;
    const int n0 = blockIdx.y * 16;
    const int b = blockIdx.z;
    extern __shared__ float xact[];  // 24 * 612
    __shared__ float we[192], wd[216];
    __shared__ float g1s[24], b1s[24];
    __shared__ float mu1[3], rs1[3];
    __shared__ float red[6];
    const int t = threadIdx.x;
    if (t < 192) we[t] = W_exp[t];
    if (t < 216) wd[t] = W_dw[t];
    if (t < 24) { g1s[t] = g1[t]; b1s[t] = b1[t]; }
    if (t < 3) {
        const float cnt = 2097152.f;
        float s = S_stats1[b * 6 + 2 * t], qq = S_stats1[b * 6 + 2 * t + 1];
        float m = s / cnt;
        mu1[t] = m;
        rs1[t] = rsqrtf(qq / cnt - m * m + EPS_);
    }
    if (t < 6) red[t] = 0.f;
    __syncthreads();

    // Phase 1: activated expand tile with halo
#pragma unroll 1
    for (int idx = t; idx < 612; idx += 256) {
        int i = idx / 34, j = idx - i * 34;
        int gi = n0 - 1 + i, gj = m0 - 1 + j;
        if ((unsigned)gi < 1024u && (unsigned)gj < 256u) {
            const __half* A = S_attn + (size_t)b * 2097152 + gi * 256 + gj;
            float a[8];
#pragma unroll
            for (int h = 0; h < 8; h++) a[h] = __half2float(A[h * 262144]);
#pragma unroll
            for (int o = 0; o < 24; o++) {
                float x = 0.f;
#pragma unroll
                for (int h = 0; h < 8; h++) x += we[o * 8 + h] * a[h];
                int g = o >> 3;
                x = (x - mu1[g]) * rs1[g] * g1s[o] + b1s[o];
                xact[o * 612 + idx] = fswish(x);
            }
        } else {
#pragma unroll
            for (int o = 0; o < 24; o++) xact[o * 612 + idx] = 0.f;
        }
    }
    __syncthreads();

    // Phase 2: warp-per-3-channels dwconv, weights in registers, j-pair pixels
    {
        const int wi = t >> 5;    // warp 0..7
        const int lane = t & 31;
        float wreg[3][9];
#pragma unroll
        for (int c = 0; c < 3; c++)
#pragma unroll
            for (int k2 = 0; k2 < 9; k2++) wreg[c][k2] = wd[(wi + c * 8) * 9 + k2];
        float sacc[3] = {0.f, 0.f, 0.f}, qacc[3] = {0.f, 0.f, 0.f};
#pragma unroll 1
        for (int k = 0; k < 8; k++) {
            int pp = lane + k * 32;       // 0..255 pixel pairs
            int i = pp >> 4, jp = (pp & 15) * 2;
            size_t gp = (size_t)(n0 + i) * 256 + (m0 + jp);
#pragma unroll
            for (int c = 0; c < 3; c++) {
                int o = wi + c * 8;
                const float* xb = xact + o * 612 + i * 34 + jp;
                float r0a = xb[0],  r0b = xb[1],  r0c = xb[2],  r0d = xb[3];
                float r1a = xb[34], r1b = xb[35], r1c = xb[36], r1d = xb[37];
                float r2a = xb[68], r2b = xb[69], r2c = xb[70], r2d = xb[71];
                const float* w = wreg[c];
                float y0 = w[0] * r0a + w[1] * r0b + w[2] * r0c
                         + w[3] * r1a + w[4] * r1b + w[5] * r1c
                         + w[6] * r2a + w[7] * r2b + w[8] * r2c;
                float y1 = w[0] * r0b + w[1] * r0c + w[2] * r0d
                         + w[3] * r1b + w[4] * r1c + w[5] * r1d
                         + w[6] * r2b + w[7] * r2c + w[8] * r2d;
                *(__half2*)&S_y[((size_t)(b * 24 + o)) * 262144 + gp] =
                    __floats2half2_rn(y0, y1);
                sacc[c] += y0 + y1;
                qacc[c] += y0 * y0 + y1 * y1;
            }
        }
#pragma unroll
        for (int c = 0; c < 3; c++) {
            sacc[c] = wred(sacc[c]);
            qacc[c] = wred(qacc[c]);
            if (lane == 0) {
                atomicAdd(&red[2 * c], sacc[c]);
                atomicAdd(&red[2 * c + 1], qacc[c]);
            }
        }
    }
    __syncthreads();
    if (t < 6) atomicAdd(&S_stats2[b * 6 + t], red[t]);
}

// ---------------- DLA pass 1: GN2->swish->reduce -> r(fp32) + GN3 stats ----------------
__global__ __launch_bounds__(256) void k_red(
    const float* __restrict__ g2, const float* __restrict__ b2,
    const float* __restrict__ W_red) {
    const int b = blockIdx.x;
    const int p0 = blockIdx.y * 1024;   // half2 index
    __shared__ float wrd[192], g2s[24], b2s[24];
    __shared__ float mu2[3], rs2[3];
    __shared__ float red[2];
    const int t = threadIdx.x;
    if (t < 192) wrd[t] = W_red[t];
    if (t < 24) { g2s[t] = g2[t]; b2s[t] = b2[t]; }
    if (t < 3) {
        const float cnt = 2097152.f;
        float s = S_stats2[b * 6 + 2 * t], qq = S_stats2[b * 6 + 2 * t + 1];
        float m = s / cnt;
        mu2[t] = m;
        rs2[t] = rsqrtf(qq / cnt - m * m + EPS_);
    }
    if (t < 2) red[t] = 0.f;
    __syncthreads();
    float s3 = 0, q3 = 0;
    const __half2* Y = (const __half2*)S_y + (size_t)(b * 24) * 131072;
    float* R = S_r + (size_t)b * 8 * 262144;
#pragma unroll 1
    for (int k = 0; k < 4; k++) {
        int p = p0 + k * 256 + t;
        float r0[8], r1[8];
#pragma unroll
        for (int h = 0; h < 8; h++) { r0[h] = 0.f; r1[h] = 0.f; }
#pragma unroll
        for (int o = 0; o < 24; o++) {
            float2 yf = __half22float2(Y[(size_t)o * 131072 + p]);
            int g = o >> 3;
            float sc = rs2[g] * g2s[o];
            float z0 = (yf.x - mu2[g]) * sc + b2s[o];
            float z1 = (yf.y - mu2[g]) * sc + b2s[o];
            z0 = fswish(z0);
            z1 = fswish(z1);
#pragma unroll
            for (int h = 0; h < 8; h++) {
                float w = wrd[h * 24 + o];
                r0[h] += w * z0;
                r1[h] += w * z1;
            }
        }
#pragma unroll
        for (int h = 0; h < 8; h++) {
            *(float2*)&R[(size_t)h * 262144 + 2 * p] = make_float2(r0[h], r1[h]);
            s3 += r0[h] + r1[h];
            q3 += r0[h] * r0[h] + r1[h] * r1[h];
        }
    }
    s3 = wred(s3); q3 = wred(q3);
    if ((t & 31) == 0) { atomicAdd(&red[0], s3); atomicAdd(&red[1], q3); }
    __syncthreads();
    if (t < 2) atomicAdd(&S_stats3[b * 2 + t], red[t]);
}

// ---------------- AV product (GN3 on the fly), 64-row tile, 8 accs/thread ----------------
__global__ __launch_bounds__(256) void k_av(const float* __restrict__ g3, const float* __restrict__ b3) {
    const int bh = blockIdx.x;
    const int n0 = blockIdx.y * 64;
    const int b = bh >> 3, h = bh & 7;
    extern __shared__ float sm[];
    float* vs = sm;           // 8192
    float* rs = sm + 8192;    // 16384
    __shared__ float params[2];
    if (threadIdx.x == 0) {
        const float cnt = 2097152.f;
        float s = S_stats3[b * 2], qq = S_stats3[b * 2 + 1];
        float m = s / cnt;
        float rstd = rsqrtf(qq / cnt - m * m + EPS_);
        float gh = g3[h];
        params[0] = rstd * gh;
        params[1] = b3[h] - m * rstd * gh;
    }
    __syncthreads();
    float scl = params[0], sft = params[1];
    for (int idx = threadIdx.x; idx < 8192; idx += 256)
        vs[idx] = S_v[(size_t)bh * 8192 + idx];
    const float* R = S_r + (size_t)(bh * 1024 + n0) * 256;
    for (int idx = threadIdx.x; idx < 16384; idx += 256)
        rs[idx] = R[idx] * scl + sft;
    __syncthreads();
    const int d = threadIdx.x & 31, nb = threadIdx.x >> 5;
    float acc[8];
#pragma unroll
    for (int k = 0; k < 8; k++) acc[k] = 0.f;
    for (int m = 0; m < 256; m += 4) {
        float v0 = vs[m * 32 + d];
        float v1 = vs[(m + 1) * 32 + d];
        float v2 = vs[(m + 2) * 32 + d];
        float v3 = vs[(m + 3) * 32 + d];
#pragma unroll
        for (int k = 0; k < 8; k++) {
            int nl = nb + k * 8;
            float4 rr = *(const float4*)(rs + nl * 256 + m);
            acc[k] += rr.x * v0 + rr.y * v1 + rr.z * v2 + rr.w * v3;
        }
    }
#pragma unroll
    for (int k = 0; k < 8; k++) {
        int nl = nb + k * 8;
        S_hout[(size_t)(b * 1024 + n0 + nl) * 256 + h * 32 + d] = acc[k];
    }
}

// ---------------- output projection + NCHW transpose ----------------
__global__ __launch_bounds__(256) void k_out(const float* __restrict__ Wp, const float* __restrict__ bp,
                                             float* __restrict__ out) {
    const int b = blockIdx.x;
    const int n0 = blockIdx.y * 32;
    extern __shared__ float sm2[];
    float* hs = sm2;
    for (int idx = threadIdx.x; idx < 8192; idx += 256) {
        int nl = idx >> 8, cp = idx & 255;
        hs[cp * 36 + nl] = S_hout[(size_t)(b * 1024 + n0 + nl) * 256 + cp];
    }
    __syncthreads();
    int c = threadIdx.x;
    float acc[32];
#pragma unroll
    for (int i = 0; i < 32; i++) acc[i] = 0.f;
    const float* wrow = Wp + c * 256;
    for (int cp = 0; cp < 256; cp++) {
        float w = __ldg(wrow + cp);
        const float4* h4 = (const float4*)(hs + cp * 36);
#pragma unroll
        for (int i4 = 0; i4 < 8; i4++) {
            float4 hh = h4[i4];
            acc[i4 * 4 + 0] += hh.x * w;
            acc[i4 * 4 + 1] += hh.y * w;
            acc[i4 * 4 + 2] += hh.z * w;
            acc[i4 * 4 + 3] += hh.w * w;
        }
    }
    float bpc = bp[c];
    __syncthreads();
    float* os = sm2;
#pragma unroll
    for (int i = 0; i < 32; i++) os[c * 36 + i] = acc[i] + bpc;
    __syncthreads();
    for (int idx = threadIdx.x; idx < 8192; idx += 256) {
        int c2 = idx >> 5, i2 = idx & 31;
        out[((size_t)b * 256 + c2) * 1024 + n0 + i2] = os[c2 * 36 + i2];
    }
}

// ---------------- host launcher ----------------
extern "C" void kernel_launch(void* const* d_in, const int* in_sizes, int n_in,
                              void* d_out, int out_size) {
    const float* q     = (const float*)d_in[0];
    const float* kv    = (const float*)d_in[1];
    const float* Wq    = (const float*)d_in[2];
    const float* Wkv   = (const float*)d_in[3];
    const float* Wp    = (const float*)d_in[4];
    const float* bp    = (const float*)d_in[5];
    const float* rpb   = (const float*)d_in[6];
    const float* W_exp = (const float*)d_in[7];
    const float* g1    = (const float*)d_in[8];
    const float* b1    = (const float*)d_in[9];
    const float* W_dw  = (const float*)d_in[10];
    const float* g2    = (const float*)d_in[11];
    const float* b2    = (const float*)d_in[12];
    const float* W_red = (const float*)d_in[13];
    const float* g3    = (const float*)d_in[14];
    const float* b3    = (const float*)d_in[15];
    float* out = (float*)d_out;

    cudaFuncSetAttribute(k_dla0, cudaFuncAttributeMaxDynamicSharedMemorySize, 24 * 612 * 4);
    cudaFuncSetAttribute(k_av, cudaFuncAttributeMaxDynamicSharedMemorySize, 98304);
    cudaFuncSetAttribute(k_out, cudaFuncAttributeMaxDynamicSharedMemorySize, 256 * 36 * 4);

    k_all_proj<<<dim3(16, 48), 256>>>(q, Wq, kv, Wkv);
    k_attn<<<dim3(128, 16), 256>>>(rpb);
    k_gram<<<dim3(16, 32), 256>>>();
    k_stats1p<<<1, 64>>>(W_exp);
    k_dla0<<<dim3(8, 64, 16), 256, 24 * 612 * 4>>>(W_exp, g1, b1, W_dw);
    k_red<<<dim3(16, 128), 256>>>(g2, b2, W_red);
    k_av<<<dim3(128, 16), 256, 98304>>>(g3, b3);
    k_out<<<dim3(16, 32), 256, 256 * 36 * 4>>>(Wp, bp, out);
}

// round 12
// speedup vs baseline: 1.0334x; 1.0334x over previous
#include <cuda_runtime.h>
#include <math.h>

#define B_   16
#define C_   256
#define NH_  8
#define HD_  32
#define N_   1024
#define M_   256
#define HID_ 24
#define EPS_ 1e-5f

typedef unsigned long long u64t;

// ---------------- scratch ----------------
__device__ float S_q[B_ * NH_ * N_ * HD_];
__device__ float S_k[B_ * NH_ * M_ * HD_];
__device__ float S_v[B_ * NH_ * M_ * HD_];
__device__ float S_attn[B_ * NH_ * N_ * M_];   // 134 MB
__device__ float S_y[B_ * HID_ * N_ * M_];     // 403 MB
__device__ float S_r[B_ * NH_ * N_ * M_];      // 134 MB
__device__ float S_hout[B_ * N_ * C_];
__device__ float S_gram[B_ * 36];
__device__ float S_stats1[B_ * 3 * 2];
__device__ float S_stats2[B_ * 3 * 2];
__device__ float S_stats3[B_ * 2];

__device__ __forceinline__ float wred(float v) {
#pragma unroll
    for (int o = 16; o; o >>= 1) v += __shfl_xor_sync(0xffffffffu, v, o);
    return v;
}
__device__ __forceinline__ float tanh_fast(float x) {
    float y;
    asm("tanh.approx.f32 %0, %1;" : "=f"(y) : "f"(x));
    return y;
}
__device__ __forceinline__ float fswish(float x) {
    return 0.5f * x * (1.f + tanh_fast(0.5f * x));
}
// ---- packed f32x2 helpers (FFMA2 path; ptxas never emits these from C++) ----
__device__ __forceinline__ u64t pk2(float lo, float hi) {
    u64t r;
    asm("mov.b64 %0, {%1, %2};" : "=l"(r) : "f"(lo), "f"(hi));
    return r;
}
__device__ __forceinline__ float2 upk2(u64t v) {
    float2 f;
    asm("mov.b64 {%0, %1}, %2;" : "=f"(f.x), "=f"(f.y) : "l"(v));
    return f;
}
__device__ __forceinline__ u64t ffma2(u64t a, u64t b, u64t c) {
    u64t d;
    asm("fma.rn.f32x2 %0, %1, %2, %3;" : "=l"(d) : "l"(a), "l"(b), "l"(c));
    return d;
}
__device__ __forceinline__ u64t fadd2(u64t a, u64t b) {
    u64t d;
    asm("add.rn.f32x2 %0, %1, %2;" : "=l"(d) : "l"(a), "l"(b));
    return d;
}

// ---------------- fused projections (q + kv) + scratch zeroing ----------------
__global__ __launch_bounds__(256) void k_all_proj(
    const float* __restrict__ q, const float* __restrict__ Wq,
    const float* __restrict__ kv, const float* __restrict__ Wkv) {
    __shared__ float sbuf[8192];
    const int b = blockIdx.x;
    const int y = blockIdx.y;
    const int t = threadIdx.x;
    if (b == 0 && y == 0) {
        for (int i = t; i < 576; i += 256) S_gram[i] = 0.f;
        if (t < 96) S_stats2[t] = 0.f;
        if (t < 32) S_stats3[t] = 0.f;
    }
    if (y < 32) {
        const int n0 = y * 32;
        for (int idx = t; idx < 2048; idx += 256) {
            int c = idx >> 3, i4 = idx & 7;
            ((float4*)sbuf)[idx] = ((const float4*)(q + (b * 256 + c) * 1024 + n0))[i4];
        }
        __syncthreads();
        float acc[32];
#pragma unroll
        for (int i = 0; i < 32; i++) acc[i] = 0.f;
        const float* wrow = Wq + t * 256;
        for (int c = 0; c < 256; c++) {
            float w = __ldg(wrow + c);
            const float4* q4 = (const float4*)(sbuf + c * 32);
#pragma unroll
            for (int i4 = 0; i4 < 8; i4++) {
                float4 qq = q4[i4];
                acc[i4 * 4 + 0] += qq.x * w;
                acc[i4 * 4 + 1] += qq.y * w;
                acc[i4 * 4 + 2] += qq.z * w;
                acc[i4 * 4 + 3] += qq.w * w;
            }
        }
        int h = t >> 5, d = t & 31;
#pragma unroll
        for (int i = 0; i < 32; i++)
            S_q[((b * 8 + h) * 1024 + n0 + i) * 32 + d] = acc[i];
    } else {
        const int m0 = (y - 32) * 16;
        for (int idx = t; idx < 4096; idx += 256) {
            int c = idx >> 4, i = idx & 15;
            sbuf[c * 16 + i] = kv[(b * 256 + c) * 256 + m0 + i];
        }
        __syncthreads();
        for (int jj = 0; jj < 2; jj++) {
            int j = t + jj * 256;
            float acc[16];
#pragma unroll
            for (int i = 0; i < 16; i++) acc[i] = 0.f;
            const float* wrow = Wkv + j * 256;
            for (int c = 0; c < 256; c++) {
                float w = __ldg(wrow + c);
                const float4* k4 = (const float4*)(sbuf + c * 16);
#pragma unroll
                for (int i4 = 0; i4 < 4; i4++) {
                    float4 kk = k4[i4];
                    acc[i4 * 4 + 0] += kk.x * w;
                    acc[i4 * 4 + 1] += kk.y * w;
                    acc[i4 * 4 + 2] += kk.z * w;
                    acc[i4 * 4 + 3] += kk.w * w;
                }
            }
            float* dst = (j < 256) ? S_k : S_v;
            int hd = j & 255;
            int h = hd >> 5, d = hd & 31;
#pragma unroll
            for (int i = 0; i < 16; i++)
                dst[((b * 8 + h) * 256 + m0 + i) * 32 + d] = acc[i];
        }
    }
}

// ---------------- attention: register-tiled QK^T + softmax (fp32) ----------------
__global__ __launch_bounds__(256) void k_attn(const float* __restrict__ rpb) {
    const int bh = blockIdx.x;
    const int n0 = blockIdx.y * 64;
    __shared__ float Qs[32 * 68];
    __shared__ float Ks[32 * 260];
    const int t = threadIdx.x;
    {
        const int d = t & 31, g = t >> 5;
        const float* qsrc = S_q + (size_t)(bh * 1024 + n0) * 32 + d;
#pragma unroll
        for (int i = 0; i < 8; i++)
            Qs[d * 68 + g * 8 + i] = qsrc[(g * 8 + i) * 32];
        const float* ksrc = S_k + (size_t)bh * 8192 + d;
#pragma unroll
        for (int i = 0; i < 32; i++)
            Ks[d * 260 + g * 32 + i] = ksrc[(g * 32 + i) * 32];
    }
    __syncthreads();
    const int mg = t & 31;
    const int ng = t >> 5;
    float acc[8][8];
#pragma unroll
    for (int i = 0; i < 8; i++)
#pragma unroll
        for (int j = 0; j < 8; j++) acc[i][j] = 0.f;
#pragma unroll 4
    for (int k = 0; k < 32; k++) {
        float4 q0 = *(const float4*)&Qs[k * 68 + ng * 8];
        float4 q1 = *(const float4*)&Qs[k * 68 + ng * 8 + 4];
        float4 k0 = *(const float4*)&Ks[k * 260 + mg * 8];
        float4 k1 = *(const float4*)&Ks[k * 260 + mg * 8 + 4];
        float qv[8] = {q0.x, q0.y, q0.z, q0.w, q1.x, q1.y, q1.z, q1.w};
        float kw[8] = {k0.x, k0.y, k0.z, k0.w, k1.x, k1.y, k1.z, k1.w};
#pragma unroll
        for (int i = 0; i < 8; i++)
#pragma unroll
            for (int j = 0; j < 8; j++) acc[i][j] += qv[i] * kw[j];
    }
    const float scale = 0.17677669529663689f;
#pragma unroll
    for (int i = 0; i < 8; i++) {
        const int n = n0 + ng * 8 + i;
        const float* rp = rpb + (size_t)n * 256 + mg * 8;
        float4 r0 = *(const float4*)rp;
        float4 r1 = *(const float4*)(rp + 4);
        float rb[8] = {r0.x, r0.y, r0.z, r0.w, r1.x, r1.y, r1.z, r1.w};
        float mx = -1e30f;
#pragma unroll
        for (int j = 0; j < 8; j++) {
            acc[i][j] = acc[i][j] * scale + rb[j];
            mx = fmaxf(mx, acc[i][j]);
        }
#pragma unroll
        for (int o = 16; o; o >>= 1) mx = fmaxf(mx, __shfl_xor_sync(0xffffffffu, mx, o));
        float s = 0.f;
#pragma unroll
        for (int j = 0; j < 8; j++) {
            float e = __expf(acc[i][j] - mx);
            acc[i][j] = e;
            s += e;
        }
        s = wred(s);
        float inv = __fdividef(1.f, s);
        float* dst = S_attn + (size_t)(bh * 1024 + n) * 256 + mg * 8;
        float4 o0 = make_float4(acc[i][0] * inv, acc[i][1] * inv, acc[i][2] * inv, acc[i][3] * inv);
        float4 o1 = make_float4(acc[i][4] * inv, acc[i][5] * inv, acc[i][6] * inv, acc[i][7] * inv);
        *(float4*)dst = o0;
        *(float4*)(dst + 4) = o1;
    }
}

// ---------------- head Gram matrix ----------------
__global__ __launch_bounds__(256) void k_gram() {
    const int b = blockIdx.x;
    const int base = blockIdx.y * 8192 + threadIdx.x;
    __shared__ float gs[36];
    const int t = threadIdx.x;
    if (t < 36) gs[t] = 0.f;
    __syncthreads();
    float g[36];
#pragma unroll
    for (int c = 0; c < 36; c++) g[c] = 0.f;
    const float* A = S_attn + (size_t)b * 2097152;
#pragma unroll 1
    for (int k = 0; k < 32; k++) {
        int pix = base + k * 256;
        float a[8];
#pragma unroll
        for (int h = 0; h < 8; h++) a[h] = A[h * 262144 + pix];
        int c = 0;
#pragma unroll
        for (int i = 0; i < 8; i++)
#pragma unroll
            for (int j = i; j < 8; j++) g[c++] += a[i] * a[j];
    }
#pragma unroll
    for (int c = 0; c < 36; c++) {
        g[c] = wred(g[c]);
        if ((t & 31) == 0) atomicAdd(&gs[c], g[c]);
    }
    __syncthreads();
    if (t < 36) atomicAdd(&S_gram[b * 36 + t], gs[t]);
}

// ---------------- derive GN1 stats analytically ----------------
__global__ void k_stats1p(const float* __restrict__ W_exp) {
    const int t = threadIdx.x;
    if (t >= 48) return;
    const int b = t / 3, g = t % 3;
    float sumw = 0.f, sumxx = 0.f;
    const float* G = S_gram + b * 36;
    for (int o = g * 8; o < g * 8 + 8; o++) {
        float wo[8];
#pragma unroll
        for (int h = 0; h < 8; h++) wo[h] = W_exp[o * 8 + h];
#pragma unroll
        for (int h = 0; h < 8; h++) sumw += wo[h];
#pragma unroll
        for (int i = 0; i < 8; i++)
#pragma unroll
            for (int j = 0; j < 8; j++) {
                int a = i < j ? i : j, bb = i < j ? j : i;
                sumxx += wo[i] * wo[j] * G[8 * a - a * (a - 1) / 2 + (bb - a)];
            }
    }
    S_stats1[b * 6 + 2 * g] = sumw * 1024.f;
    S_stats1[b * 6 + 2 * g + 1] = sumxx;
}

// ---------------- DLA pass 0: packed f32x2 expand + dwconv ----------------
__global__ __launch_bounds__(256, 3) void k_dla0(
    const float* __restrict__ W_exp, const float* __restrict__ g1,
    const float* __restrict__ b1, const float* __restrict__ W_dw) {
    const int m0 = blockIdx.x * 32;
    const int n0 = blockIdx.y * 16;
    const int b = blockIdx.z;
    extern __shared__ float xact[];  // 24 * 612 floats
    __shared__ float wd[216];
    __shared__ float g1s[24], b1s[24];
    __shared__ float mu1[3], rs1[3];
    __shared__ u64t wes2[192];  // packed (W_exp * GN1scale)
    __shared__ u64t T2a[24];    // packed GN1 shift
    __shared__ float red[6];
    const int t = threadIdx.x;
    if (t < 216) wd[t] = W_dw[t];
    if (t < 24) { g1s[t] = g1[t]; b1s[t] = b1[t]; }
    if (t < 3) {
        const float cnt = 2097152.f;
        float s = S_stats1[b * 6 + 2 * t], qq = S_stats1[b * 6 + 2 * t + 1];
        float m = s / cnt;
        mu1[t] = m;
        rs1[t] = rsqrtf(qq / cnt - m * m + EPS_);
    }
    if (t < 6) red[t] = 0.f;
    __syncthreads();
    if (t < 192) {
        int o = t >> 3;
        int g = o >> 3;
        float S = rs1[g] * g1s[o];
        float w = W_exp[t] * S;
        wes2[t] = pk2(w, w);
    }
    if (t < 24) {
        int g = t >> 3;
        float S = rs1[g] * g1s[t];
        float T = b1s[t] - mu1[g] * S;
        T2a[t] = pk2(T, T);
    }
    __syncthreads();

    // Phase 1: activated expand tile (halo 18x34 = 612 entries, 306 pairs)
    const float* Ab = S_attn + (size_t)b * 2097152;
#pragma unroll 1
    for (int pi = t; pi < 306; pi += 256) {
        int e0 = 2 * pi, e1 = e0 + 1;
        int i0 = e0 / 34, j0 = e0 - 34 * i0;
        int i1 = e1 / 34, j1 = e1 - 34 * i1;
        int gi0 = n0 - 1 + i0, gj0 = m0 - 1 + j0;
        int gi1 = n0 - 1 + i1, gj1 = m0 - 1 + j1;
        bool v0 = ((unsigned)gi0 < 1024u) && ((unsigned)gj0 < 256u);
        bool v1 = ((unsigned)gi1 < 1024u) && ((unsigned)gj1 < 256u);
        const float* A0 = Ab + gi0 * 256 + gj0;
        const float* A1 = Ab + gi1 * 256 + gj1;
        u64t a2[8];
#pragma unroll
        for (int h = 0; h < 8; h++) {
            float x0 = v0 ? A0[h * 262144] : 0.f;
            float x1 = v1 ? A1[h * 262144] : 0.f;
            a2[h] = pk2(x0, x1);
        }
#pragma unroll
        for (int o = 0; o < 24; o++) {
            u64t x2 = T2a[o];
#pragma unroll
            for (int h = 0; h < 8; h++) x2 = ffma2(wes2[o * 8 + h], a2[h], x2);
            float2 f = upk2(x2);
            xact[o * 612 + e0] = v0 ? fswish(f.x) : 0.f;
            xact[o * 612 + e1] = v1 ? fswish(f.y) : 0.f;
        }
    }
    __syncthreads();

    // Phase 2: warp-per-3-channels dwconv, packed over j-pairs
    {
        const int wi = t >> 5;
        const int lane = t & 31;
#pragma unroll
        for (int c = 0; c < 3; c++) {
            const int o = wi + c * 8;
            u64t w2[9];
#pragma unroll
            for (int k2 = 0; k2 < 9; k2++) {
                float w = wd[o * 9 + k2];
                w2[k2] = pk2(w, w);
            }
            u64t ss = pk2(0.f, 0.f), qq = pk2(0.f, 0.f);
#pragma unroll 1
            for (int k = 0; k < 8; k++) {
                int pp = lane + k * 32;
                int i = pp >> 4, jp = (pp & 15) * 2;
                const float* xb = xact + o * 612 + i * 34 + jp;
                float2 A0 = *(const float2*)(xb);
                float2 B0 = *(const float2*)(xb + 2);
                float2 A1 = *(const float2*)(xb + 34);
                float2 B1 = *(const float2*)(xb + 36);
                float2 A2 = *(const float2*)(xb + 68);
                float2 B2 = *(const float2*)(xb + 70);
                u64t y2 = pk2(0.f, 0.f);
                y2 = ffma2(w2[0], pk2(A0.x, A0.y), y2);
                y2 = ffma2(w2[1], pk2(A0.y, B0.x), y2);
                y2 = ffma2(w2[2], pk2(B0.x, B0.y), y2);
                y2 = ffma2(w2[3], pk2(A1.x, A1.y), y2);
                y2 = ffma2(w2[4], pk2(A1.y, B1.x), y2);
                y2 = ffma2(w2[5], pk2(B1.x, B1.y), y2);
                y2 = ffma2(w2[6], pk2(A2.x, A2.y), y2);
                y2 = ffma2(w2[7], pk2(A2.y, B2.x), y2);
                y2 = ffma2(w2[8], pk2(B2.x, B2.y), y2);
                size_t gp = (size_t)(n0 + i) * 256 + (m0 + jp);
                float2 yo = upk2(y2);
                *(float2*)&S_y[((size_t)(b * 24 + o)) * 262144 + gp] = yo;
                ss = fadd2(ss, y2);
                qq = ffma2(y2, y2, qq);
            }
            float2 sf = upk2(ss), qf = upk2(qq);
            float sa = wred(sf.x + sf.y);
            float qa = wred(qf.x + qf.y);
            if (lane == 0) {
                atomicAdd(&red[2 * c], sa);
                atomicAdd(&red[2 * c + 1], qa);
            }
        }
    }
    __syncthreads();
    if (t < 6) atomicAdd(&S_stats2[b * 6 + t], red[t]);
}

// ---------------- DLA pass 1: packed f32x2 GN2->swish->reduce ----------------
__global__ __launch_bounds__(256) void k_red(
    const float* __restrict__ g2, const float* __restrict__ b2,
    const float* __restrict__ W_red) {
    const int b = blockIdx.x;
    const int p0 = blockIdx.y * 1024;  // pair index; grid.y = 128
    __shared__ u64t wrd2[192];
    __shared__ float g2s[24], b2s[24];
    __shared__ float mu2[3], rs2[3];
    __shared__ u64t S2[24], T2[24];
    __shared__ float red[2];
    const int t = threadIdx.x;
    if (t < 192) {
        float w = W_red[t];
        wrd2[t] = pk2(w, w);
    }
    if (t < 24) { g2s[t] = g2[t]; b2s[t] = b2[t]; }
    if (t < 3) {
        const float cnt = 2097152.f;
        float s = S_stats2[b * 6 + 2 * t], qq = S_stats2[b * 6 + 2 * t + 1];
        float m = s / cnt;
        mu2[t] = m;
        rs2[t] = rsqrtf(qq / cnt - m * m + EPS_);
    }
    if (t < 2) red[t] = 0.f;
    __syncthreads();
    if (t < 24) {
        int g = t >> 3;
        float S = rs2[g] * g2s[t];
        float T = b2s[t] - mu2[g] * S;
        S2[t] = pk2(S, S);
        T2[t] = pk2(T, T);
    }
    __syncthreads();
    u64t s3_2 = pk2(0.f, 0.f), q3_2 = pk2(0.f, 0.f);
    const float* Y = S_y + (size_t)b * 24 * 262144;
    float* R = S_r + (size_t)b * 8 * 262144;
#pragma unroll 1
    for (int k = 0; k < 4; k++) {
        int pr = p0 + k * 256 + t;
        u64t r2[8];
#pragma unroll
        for (int h = 0; h < 8; h++) r2[h] = pk2(0.f, 0.f);
#pragma unroll
        for (int o = 0; o < 24; o++) {
            float2 yf = ((const float2*)(Y + (size_t)o * 262144))[pr];
            u64t y2 = ffma2(S2[o], pk2(yf.x, yf.y), T2[o]);
            float2 f = upk2(y2);
            u64t z2 = pk2(fswish(f.x), fswish(f.y));
#pragma unroll
            for (int h = 0; h < 8; h++) r2[h] = ffma2(wrd2[h * 24 + o], z2, r2[h]);
        }
#pragma unroll
        for (int h = 0; h < 8; h++) {
            ((float2*)(R + (size_t)h * 262144))[pr] = upk2(r2[h]);
            s3_2 = fadd2(s3_2, r2[h]);
            q3_2 = ffma2(r2[h], r2[h], q3_2);
        }
    }
    float2 sf = upk2(s3_2), qf = upk2(q3_2);
    float s3 = wred(sf.x + sf.y);
    float q3 = wred(qf.x + qf.y);
    if ((t & 31) == 0) { atomicAdd(&red[0], s3); atomicAdd(&red[1], q3); }
    __syncthreads();
    if (t < 2) atomicAdd(&S_stats3[b * 2 + t], red[t]);
}

// ---------------- AV product (GN3 on the fly) ----------------
__global__ __launch_bounds__(256) void k_av(const float* __restrict__ g3, const float* __restrict__ b3) {
    const int bh = blockIdx.x;
    const int n0 = blockIdx.y * 32;
    const int b = bh >> 3, h = bh & 7;
    extern __shared__ float sm[];
    float* vs = sm;          // 8192
    float* rs = sm + 8192;   // 8192
    __shared__ float params[2];
    if (threadIdx.x == 0) {
        const float cnt = 2097152.f;
        float s = S_stats3[b * 2], qq = S_stats3[b * 2 + 1];
        float m = s / cnt;
        float rstd = rsqrtf(qq / cnt - m * m + EPS_);
        float gh = g3[h];
        params[0] = rstd * gh;
        params[1] = b3[h] - m * rstd * gh;
    }
    __syncthreads();
    float scl = params[0], sft = params[1];
    for (int idx = threadIdx.x; idx < 8192; idx += 256)
        vs[idx] = S_v[(size_t)bh * 8192 + idx];
    const float* R = S_r + (size_t)(bh * 1024 + n0) * 256;
    for (int idx = threadIdx.x; idx < 8192; idx += 256)
        rs[idx] = R[idx] * scl + sft;
    __syncthreads();
    const int d = threadIdx.x & 31, nb = threadIdx.x >> 5;
    float acc[4];
#pragma unroll
    for (int k = 0; k < 4; k++) acc[k] = 0.f;
    for (int m = 0; m < 256; m += 4) {
        float v0 = vs[m * 32 + d];
        float v1 = vs[(m + 1) * 32 + d];
        float v2 = vs[(m + 2) * 32 + d];
        float v3 = vs[(m + 3) * 32 + d];
#pragma unroll
        for (int k = 0; k < 4; k++) {
            int nl = nb + k * 8;
            float4 rr = *(const float4*)(rs + nl * 256 + m);
            acc[k] += rr.x * v0 + rr.y * v1 + rr.z * v2 + rr.w * v3;
        }
    }
#pragma unroll
    for (int k = 0; k < 4; k++) {
        int nl = nb + k * 8;
        S_hout[(size_t)(b * 1024 + n0 + nl) * 256 + h * 32 + d] = acc[k];
    }
}

// ---------------- output projection + NCHW transpose ----------------
__global__ __launch_bounds__(256) void k_out(const float* __restrict__ Wp, const float* __restrict__ bp,
                                             float* __restrict__ out) {
    const int b = blockIdx.x;
    const int n0 = blockIdx.y * 32;
    extern __shared__ float sm2[];
    float* hs = sm2;
    for (int idx = threadIdx.x; idx < 8192; idx += 256) {
        int nl = idx >> 8, cp = idx & 255;
        hs[cp * 36 + nl] = S_hout[(size_t)(b * 1024 + n0 + nl) * 256 + cp];
    }
    __syncthreads();
    int c = threadIdx.x;
    float acc[32];
#pragma unroll
    for (int i = 0; i < 32; i++) acc[i] = 0.f;
    const float* wrow = Wp + c * 256;
    for (int cp = 0; cp < 256; cp++) {
        float w = __ldg(wrow + cp);
        const float4* h4 = (const float4*)(hs + cp * 36);
#pragma unroll
        for (int i4 = 0; i4 < 8; i4++) {
            float4 hh = h4[i4];
            acc[i4 * 4 + 0] += hh.x * w;
            acc[i4 * 4 + 1] += hh.y * w;
            acc[i4 * 4 + 2] += hh.z * w;
            acc[i4 * 4 + 3] += hh.w * w;
        }
    }
    float bpc = bp[c];
    __syncthreads();
    float* os = sm2;
#pragma unroll
    for (int i = 0; i < 32; i++) os[c * 36 + i] = acc[i] + bpc;
    __syncthreads();
    for (int idx = threadIdx.x; idx < 8192; idx += 256) {
        int c2 = idx >> 5, i2 = idx & 31;
        out[((size_t)b * 256 + c2) * 1024 + n0 + i2] = os[c2 * 36 + i2];
    }
}

// ---------------- host launcher ----------------
extern "C" void kernel_launch(void* const* d_in, const int* in_sizes, int n_in,
                              void* d_out, int out_size) {
    const float* q     = (const float*)d_in[0];
    const float* kv    = (const float*)d_in[1];
    const float* Wq    = (const float*)d_in[2];
    const float* Wkv   = (const float*)d_in[3];
    const float* Wp    = (const float*)d_in[4];
    const float* bp    = (const float*)d_in[5];
    const float* rpb   = (const float*)d_in[6];
    const float* W_exp = (const float*)d_in[7];
    const float* g1    = (const float*)d_in[8];
    const float* b1    = (const float*)d_in[9];
    const float* W_dw  = (const float*)d_in[10];
    const float* g2    = (const float*)d_in[11];
    const float* b2    = (const float*)d_in[12];
    const float* W_red = (const float*)d_in[13];
    const float* g3    = (const float*)d_in[14];
    const float* b3    = (const float*)d_in[15];
    float* out = (float*)d_out;

    cudaFuncSetAttribute(k_dla0, cudaFuncAttributeMaxDynamicSharedMemorySize, 24 * 612 * 4);
    cudaFuncSetAttribute(k_av, cudaFuncAttributeMaxDynamicSharedMemorySize, 65536);
    cudaFuncSetAttribute(k_out, cudaFuncAttributeMaxDynamicSharedMemorySize, 256 * 36 * 4);

    k_all_proj<<<dim3(16, 48), 256>>>(q, Wq, kv, Wkv);
    k_attn<<<dim3(128, 16), 256>>>(rpb);
    k_gram<<<dim3(16, 32), 256>>>();
    k_stats1p<<<1, 64>>>(W_exp);
    k_dla0<<<dim3(8, 64, 16), 256, 24 * 612 * 4>>>(W_exp, g1, b1, W_dw);
    k_red<<<dim3(16, 128), 256>>>(g2, b2, W_red);
    k_av<<<dim3(128, 32), 256, 65536>>>(g3, b3);
    k_out<<<dim3(16, 32), 256, 256 * 36 * 4>>>(Wp, bp, out);
}

// round 13
// speedup vs baseline: 1.2239x; 1.1843x over previous
#include <cuda_runtime.h>
#include <math.h>

#define B_   16
#define C_   256
#define NH_  8
#define HD_  32
#define N_   1024
#define M_   256
#define HID_ 24
#define EPS_ 1e-5f

// ---------------- scratch ----------------
__device__ float S_q[B_ * NH_ * N_ * HD_];
__device__ float S_k[B_ * NH_ * M_ * HD_];
__device__ float S_v[B_ * NH_ * M_ * HD_];
__device__ float S_attn[B_ * NH_ * N_ * M_];   // 134 MB
__device__ float S_y[B_ * HID_ * N_ * M_];     // 403 MB
__device__ float S_r[B_ * NH_ * N_ * M_];      // 134 MB
__device__ float S_hout[B_ * N_ * C_];
__device__ float S_gram[B_ * 36];
__device__ float S_stats2[B_ * 3 * 2];
__device__ float S_stats3[B_ * 2];

__device__ __forceinline__ float wred(float v) {
#pragma unroll
    for (int o = 16; o; o >>= 1) v += __shfl_xor_sync(0xffffffffu, v, o);
    return v;
}
__device__ __forceinline__ float tanh_fast(float x) {
    float y;
    asm("tanh.approx.f32 %0, %1;" : "=f"(y) : "f"(x));
    return y;
}
__device__ __forceinline__ float fswish(float x) {
    return 0.5f * x * (1.f + tanh_fast(0.5f * x));
}

// ---------------- fused projections (q + kv) + scratch zeroing ----------------
__global__ __launch_bounds__(256) void k_all_proj(
    const float* __restrict__ q, const float* __restrict__ Wq,
    const float* __restrict__ kv, const float* __restrict__ Wkv) {
    __shared__ float sbuf[8192];
    const int b = blockIdx.x;
    const int y = blockIdx.y;
    const int t = threadIdx.x;
    if (b == 0 && y == 0) {
        for (int i = t; i < 576; i += 256) S_gram[i] = 0.f;
        if (t < 96) S_stats2[t] = 0.f;
        if (t < 32) S_stats3[t] = 0.f;
    }
    if (y < 32) {
        const int n0 = y * 32;
        for (int idx = t; idx < 2048; idx += 256) {
            int c = idx >> 3, i4 = idx & 7;
            ((float4*)sbuf)[idx] = ((const float4*)(q + (b * 256 + c) * 1024 + n0))[i4];
        }
        __syncthreads();
        float acc[32];
#pragma unroll
        for (int i = 0; i < 32; i++) acc[i] = 0.f;
        const float* wrow = Wq + t * 256;
        for (int c = 0; c < 256; c++) {
            float w = __ldg(wrow + c);
            const float4* q4 = (const float4*)(sbuf + c * 32);
#pragma unroll
            for (int i4 = 0; i4 < 8; i4++) {
                float4 qq = q4[i4];
                acc[i4 * 4 + 0] += qq.x * w;
                acc[i4 * 4 + 1] += qq.y * w;
                acc[i4 * 4 + 2] += qq.z * w;
                acc[i4 * 4 + 3] += qq.w * w;
            }
        }
        int h = t >> 5, d = t & 31;
#pragma unroll
        for (int i = 0; i < 32; i++)
            S_q[((b * 8 + h) * 1024 + n0 + i) * 32 + d] = acc[i];
    } else {
        const int m0 = (y - 32) * 16;
        for (int idx = t; idx < 4096; idx += 256) {
            int c = idx >> 4, i = idx & 15;
            sbuf[c * 16 + i] = kv[(b * 256 + c) * 256 + m0 + i];
        }
        __syncthreads();
        for (int jj = 0; jj < 2; jj++) {
            int j = t + jj * 256;
            float acc[16];
#pragma unroll
            for (int i = 0; i < 16; i++) acc[i] = 0.f;
            const float* wrow = Wkv + j * 256;
            for (int c = 0; c < 256; c++) {
                float w = __ldg(wrow + c);
                const float4* k4 = (const float4*)(sbuf + c * 16);
#pragma unroll
                for (int i4 = 0; i4 < 4; i4++) {
                    float4 kk = k4[i4];
                    acc[i4 * 4 + 0] += kk.x * w;
                    acc[i4 * 4 + 1] += kk.y * w;
                    acc[i4 * 4 + 2] += kk.z * w;
                    acc[i4 * 4 + 3] += kk.w * w;
                }
            }
            float* dst = (j < 256) ? S_k : S_v;
            int hd = j & 255;
            int h = hd >> 5, d = hd & 31;
#pragma unroll
            for (int i = 0; i < 16; i++)
                dst[((b * 8 + h) * 256 + m0 + i) * 32 + d] = acc[i];
        }
    }
}

// ---------------- attention: register-tiled QK^T + softmax (fp32) ----------------
__global__ __launch_bounds__(256) void k_attn(const float* __restrict__ rpb) {
    const int bh = blockIdx.x;
    const int n0 = blockIdx.y * 64;
    __shared__ float Qs[32 * 68];
    __shared__ float Ks[32 * 260];
    const int t = threadIdx.x;
    {
        const int d = t & 31, g = t >> 5;
        const float* qsrc = S_q + (size_t)(bh * 1024 + n0) * 32 + d;
#pragma unroll
        for (int i = 0; i < 8; i++)
            Qs[d * 68 + g * 8 + i] = qsrc[(g * 8 + i) * 32];
        const float* ksrc = S_k + (size_t)bh * 8192 + d;
#pragma unroll
        for (int i = 0; i < 32; i++)
            Ks[d * 260 + g * 32 + i] = ksrc[(g * 32 + i) * 32];
    }
    __syncthreads();
    const int mg = t & 31;
    const int ng = t >> 5;
    float acc[8][8];
#pragma unroll
    for (int i = 0; i < 8; i++)
#pragma unroll
        for (int j = 0; j < 8; j++) acc[i][j] = 0.f;
#pragma unroll 4
    for (int k = 0; k < 32; k++) {
        float4 q0 = *(const float4*)&Qs[k * 68 + ng * 8];
        float4 q1 = *(const float4*)&Qs[k * 68 + ng * 8 + 4];
        float4 k0 = *(const float4*)&Ks[k * 260 + mg * 8];
        float4 k1 = *(const float4*)&Ks[k * 260 + mg * 8 + 4];
        float qv[8] = {q0.x, q0.y, q0.z, q0.w, q1.x, q1.y, q1.z, q1.w};
        float kw[8] = {k0.x, k0.y, k0.z, k0.w, k1.x, k1.y, k1.z, k1.w};
#pragma unroll
        for (int i = 0; i < 8; i++)
#pragma unroll
            for (int j = 0; j < 8; j++) acc[i][j] += qv[i] * kw[j];
    }
    const float scale = 0.17677669529663689f;
#pragma unroll
    for (int i = 0; i < 8; i++) {
        const int n = n0 + ng * 8 + i;
        const float* rp = rpb + (size_t)n * 256 + mg * 8;
        float4 r0 = *(const float4*)rp;
        float4 r1 = *(const float4*)(rp + 4);
        float rb[8] = {r0.x, r0.y, r0.z, r0.w, r1.x, r1.y, r1.z, r1.w};
        float mx = -1e30f;
#pragma unroll
        for (int j = 0; j < 8; j++) {
            acc[i][j] = acc[i][j] * scale + rb[j];
            mx = fmaxf(mx, acc[i][j]);
        }
#pragma unroll
        for (int o = 16; o; o >>= 1) mx = fmaxf(mx, __shfl_xor_sync(0xffffffffu, mx, o));
        float s = 0.f;
#pragma unroll
        for (int j = 0; j < 8; j++) {
            float e = __expf(acc[i][j] - mx);
            acc[i][j] = e;
            s += e;
        }
        s = wred(s);
        float inv = __fdividef(1.f, s);
        float* dst = S_attn + (size_t)(bh * 1024 + n) * 256 + mg * 8;
        float4 o0 = make_float4(acc[i][0] * inv, acc[i][1] * inv, acc[i][2] * inv, acc[i][3] * inv);
        float4 o1 = make_float4(acc[i][4] * inv, acc[i][5] * inv, acc[i][6] * inv, acc[i][7] * inv);
        *(float4*)dst = o0;
        *(float4*)(dst + 4) = o1;
    }
}

// ---------------- head Gram matrix ----------------
__global__ __launch_bounds__(256) void k_gram() {
    const int b = blockIdx.x;
    const int base = blockIdx.y * 8192 + threadIdx.x;
    __shared__ float gs[36];
    const int t = threadIdx.x;
    if (t < 36) gs[t] = 0.f;
    __syncthreads();
    float g[36];
#pragma unroll
    for (int c = 0; c < 36; c++) g[c] = 0.f;
    const float* A = S_attn + (size_t)b * 2097152;
#pragma unroll 1
    for (int k = 0; k < 32; k++) {
        int pix = base + k * 256;
        float a[8];
#pragma unroll
        for (int h = 0; h < 8; h++) a[h] = A[h * 262144 + pix];
        int c = 0;
#pragma unroll
        for (int i = 0; i < 8; i++)
#pragma unroll
            for (int j = i; j < 8; j++) g[c++] += a[i] * a[j];
    }
#pragma unroll
    for (int c = 0; c < 36; c++) {
        g[c] = wred(g[c]);
        if ((t & 31) == 0) atomicAdd(&gs[c], g[c]);
    }
    __syncthreads();
    if (t < 36) atomicAdd(&S_gram[b * 36 + t], gs[t]);
}

// ---------------- DLA pass 0 (captured slot): stats-from-gram + expand+GN1+swish+dw3x3 ----------------
__global__ __launch_bounds__(256, 4) void k_dla0(
    const float* __restrict__ W_exp, const float* __restrict__ g1,
    const float* __restrict__ b1, const float* __restrict__ W_dw) {
    const int m0 = blockIdx.x * 32;
    const int n0 = blockIdx.y * 8;      // 8-row core tile
    const int b = blockIdx.z;
    extern __shared__ float xact[];     // 24 * 340 floats = 32640 B
    __shared__ float we[192], wd[216];
    __shared__ float g1s[24], b1s[24];
    __shared__ float Gs[36];
    __shared__ float osum[24], osq[24];
    __shared__ float mu1[3], rs1[3];
    __shared__ float red[6];
    const int t = threadIdx.x;
    if (t < 192) we[t] = W_exp[t];
    if (t < 216) wd[t] = W_dw[t];
    if (t < 24) { g1s[t] = g1[t]; b1s[t] = b1[t]; }
    if (t < 36) Gs[t] = S_gram[b * 36 + t];
    if (t < 6) red[t] = 0.f;
    __syncthreads();
    // GN1 stats analytically from Gram (one thread per channel, then combine)
    if (t < 24) {
        const int o = t;
        float wo[8];
#pragma unroll
        for (int h = 0; h < 8; h++) wo[h] = we[o * 8 + h];
        float sw = 0.f;
#pragma unroll
        for (int h = 0; h < 8; h++) sw += wo[h];
        float sxx = 0.f;
#pragma unroll
        for (int i = 0; i < 8; i++)
#pragma unroll
            for (int j = 0; j < 8; j++) {
                int a = i < j ? i : j, bb = i < j ? j : i;
                sxx += wo[i] * wo[j] * Gs[8 * a - a * (a - 1) / 2 + (bb - a)];
            }
        osum[t] = sw;
        osq[t] = sxx;
    }
    __syncthreads();
    if (t < 3) {
        float sw = 0.f, sxx = 0.f;
#pragma unroll
        for (int k = 0; k < 8; k++) { sw += osum[t * 8 + k]; sxx += osq[t * 8 + k]; }
        float m = sw * (1024.f / 2097152.f);
        mu1[t] = m;
        rs1[t] = rsqrtf(sxx * (1.f / 2097152.f) - m * m + EPS_);
    }
    __syncthreads();

    // Phase 1: activated expand tile with halo (10 x 34 = 340 entries)
    const float* Ab = S_attn + (size_t)b * 2097152;
#pragma unroll 1
    for (int idx = t; idx < 340; idx += 256) {
        int i = idx / 34, j = idx - i * 34;
        int gi = n0 - 1 + i, gj = m0 - 1 + j;
        if ((unsigned)gi < 1024u && (unsigned)gj < 256u) {
            const float* A = Ab + gi * 256 + gj;
            float a[8];
#pragma unroll
            for (int h = 0; h < 8; h++) a[h] = A[h * 262144];
#pragma unroll
            for (int o = 0; o < 24; o++) {
                float x = 0.f;
#pragma unroll
                for (int h = 0; h < 8; h++) x += we[o * 8 + h] * a[h];
                int g = o >> 3;
                x = (x - mu1[g]) * rs1[g] * g1s[o] + b1s[o];
                xact[o * 340 + idx] = fswish(x);
            }
        } else {
#pragma unroll
            for (int o = 0; o < 24; o++) xact[o * 340 + idx] = 0.f;
        }
    }
    __syncthreads();

    // Phase 2: depthwise conv over the 8x32 core (one pixel per thread)
    {
        const int i = t >> 5, j = t & 31;
        size_t gp = (size_t)(n0 + i) * 256 + (m0 + j);
        float s0 = 0, s1 = 0, s2 = 0, q0 = 0, q1 = 0, q2 = 0;
#pragma unroll 4
        for (int o = 0; o < 24; o++) {
            const float* xb = xact + o * 340 + i * 34 + j;
            const float* w = wd + o * 9;
            float y = w[0] * xb[0] + w[1] * xb[1] + w[2] * xb[2]
                    + w[3] * xb[34] + w[4] * xb[35] + w[5] * xb[36]
                    + w[6] * xb[68] + w[7] * xb[69] + w[8] * xb[70];
            S_y[((size_t)(b * 24 + o)) * 262144 + gp] = y;
            if (o < 8)       { s0 += y; q0 += y * y; }
            else if (o < 16) { s1 += y; q1 += y * y; }
            else             { s2 += y; q2 += y * y; }
        }
        s0 = wred(s0); q0 = wred(q0); s1 = wred(s1);
        q1 = wred(q1); s2 = wred(s2); q2 = wred(q2);
        if ((t & 31) == 0) {
            atomicAdd(&red[0], s0); atomicAdd(&red[1], q0);
            atomicAdd(&red[2], s1); atomicAdd(&red[3], q1);
            atomicAdd(&red[4], s2); atomicAdd(&red[5], q2);
        }
    }
    __syncthreads();
    if (t < 6) atomicAdd(&S_stats2[b * 6 + t], red[t]);
}

// ---------------- DLA pass 1: GN2->swish->1x1 reduce -> r + GN3 stats ----------------
__global__ __launch_bounds__(256) void k_red(
    const float* __restrict__ g2, const float* __restrict__ b2,
    const float* __restrict__ W_red) {
    const int b = blockIdx.x;
    const int pix0 = blockIdx.y * 2048;
    __shared__ float wrd[192], g2s[24], b2s[24];
    __shared__ float mu2[3], rs2[3];
    __shared__ float red[2];
    const int t = threadIdx.x;
    if (t < 192) wrd[t] = W_red[t];
    if (t < 24) { g2s[t] = g2[t]; b2s[t] = b2[t]; }
    if (t < 3) {
        const float cnt = 2097152.f;
        float s = S_stats2[b * 6 + 2 * t], qq = S_stats2[b * 6 + 2 * t + 1];
        float m = s / cnt;
        mu2[t] = m;
        rs2[t] = rsqrtf(qq / cnt - m * m + EPS_);
    }
    if (t < 2) red[t] = 0.f;
    __syncthreads();
    float s3 = 0, q3 = 0;
    const float* Y = S_y + (size_t)b * 24 * 262144;
    float* R = S_r + (size_t)b * 8 * 262144;
#pragma unroll 1
    for (int k = 0; k < 8; k++) {
        int pix = pix0 + k * 256 + t;
        float r[8];
#pragma unroll
        for (int h = 0; h < 8; h++) r[h] = 0.f;
#pragma unroll
        for (int o = 0; o < 24; o++) {
            float y = Y[(size_t)o * 262144 + pix];
            int g = o >> 3;
            float z = (y - mu2[g]) * rs2[g] * g2s[o] + b2s[o];
            z = fswish(z);
#pragma unroll
            for (int h = 0; h < 8; h++) r[h] += wrd[h * 24 + o] * z;
        }
#pragma unroll
        for (int h = 0; h < 8; h++) {
            R[(size_t)h * 262144 + pix] = r[h];
            s3 += r[h];
            q3 += r[h] * r[h];
        }
    }
    s3 = wred(s3); q3 = wred(q3);
    if ((t & 31) == 0) { atomicAdd(&red[0], s3); atomicAdd(&red[1], q3); }
    __syncthreads();
    if (t < 2) atomicAdd(&S_stats3[b * 2 + t], red[t]);
}

// ---------------- AV product (GN3 applied on the fly) ----------------
__global__ __launch_bounds__(256) void k_av(const float* __restrict__ g3, const float* __restrict__ b3) {
    const int bh = blockIdx.x;
    const int n0 = blockIdx.y * 32;
    const int b = bh >> 3, h = bh & 7;
    extern __shared__ float sm[];
    float* vs = sm;          // 8192
    float* rs = sm + 8192;   // 8192
    __shared__ float params[2];
    if (threadIdx.x == 0) {
        const float cnt = 2097152.f;
        float s = S_stats3[b * 2], qq = S_stats3[b * 2 + 1];
        float m = s / cnt;
        float rstd = rsqrtf(qq / cnt - m * m + EPS_);
        float gh = g3[h];
        params[0] = rstd * gh;
        params[1] = b3[h] - m * rstd * gh;
    }
    __syncthreads();
    float scl = params[0], sft = params[1];
    for (int idx = threadIdx.x; idx < 8192; idx += 256)
        vs[idx] = S_v[(size_t)bh * 8192 + idx];
    const float* R = S_r + (size_t)(bh * 1024 + n0) * 256;
    for (int idx = threadIdx.x; idx < 8192; idx += 256)
        rs[idx] = R[idx] * scl + sft;
    __syncthreads();
    const int d = threadIdx.x & 31, nb = threadIdx.x >> 5;
    float acc[4];
#pragma unroll
    for (int k = 0; k < 4; k++) acc[k] = 0.f;
    for (int m = 0; m < 256; m += 4) {
        float v0 = vs[m * 32 + d];
        float v1 = vs[(m + 1) * 32 + d];
        float v2 = vs[(m + 2) * 32 + d];
        float v3 = vs[(m + 3) * 32 + d];
#pragma unroll
        for (int k = 0; k < 4; k++) {
            int nl = nb + k * 8;
            float4 rr = *(const float4*)(rs + nl * 256 + m);
            acc[k] += rr.x * v0 + rr.y * v1 + rr.z * v2 + rr.w * v3;
        }
    }
#pragma unroll
    for (int k = 0; k < 4; k++) {
        int nl = nb + k * 8;
        S_hout[(size_t)(b * 1024 + n0 + nl) * 256 + h * 32 + d] = acc[k];
    }
}

// ---------------- output projection + NCHW transpose ----------------
__global__ __launch_bounds__(256) void k_out(const float* __restrict__ Wp, const float* __restrict__ bp,
                                             float* __restrict__ out) {
    const int b = blockIdx.x;
    const int n0 = blockIdx.y * 32;
    extern __shared__ float sm2[];
    float* hs = sm2;
    for (int idx = threadIdx.x; idx < 8192; idx += 256) {
        int nl = idx >> 8, cp = idx & 255;
        hs[cp * 36 + nl] = S_hout[(size_t)(b * 1024 + n0 + nl) * 256 + cp];
    }
    __syncthreads();
    int c = threadIdx.x;
    float acc[32];
#pragma unroll
    for (int i = 0; i < 32; i++) acc[i] = 0.f;
    const float* wrow = Wp + c * 256;
    for (int cp = 0; cp < 256; cp++) {
        float w = __ldg(wrow + cp);
        const float4* h4 = (const float4*)(hs + cp * 36);
#pragma unroll
        for (int i4 = 0; i4 < 8; i4++) {
            float4 hh = h4[i4];
            acc[i4 * 4 + 0] += hh.x * w;
            acc[i4 * 4 + 1] += hh.y * w;
            acc[i4 * 4 + 2] += hh.z * w;
            acc[i4 * 4 + 3] += hh.w * w;
        }
    }
    float bpc = bp[c];
    __syncthreads();
    float* os = sm2;
#pragma unroll
    for (int i = 0; i < 32; i++) os[c * 36 + i] = acc[i] + bpc;
    __syncthreads();
    for (int idx = threadIdx.x; idx < 8192; idx += 256) {
        int c2 = idx >> 5, i2 = idx & 31;
        out[((size_t)b * 256 + c2) * 1024 + n0 + i2] = os[c2 * 36 + i2];
    }
}

// ---------------- host launcher ----------------
extern "C" void kernel_launch(void* const* d_in, const int* in_sizes, int n_in,
                              void* d_out, int out_size) {
    const float* q     = (const float*)d_in[0];
    const float* kv    = (const float*)d_in[1];
    const float* Wq    = (const float*)d_in[2];
    const float* Wkv   = (const float*)d_in[3];
    const float* Wp    = (const float*)d_in[4];
    const float* bp    = (const float*)d_in[5];
    const float* rpb   = (const float*)d_in[6];
    const float* W_exp = (const float*)d_in[7];
    const float* g1    = (const float*)d_in[8];
    const float* b1    = (const float*)d_in[9];
    const float* W_dw  = (const float*)d_in[10];
    const float* g2    = (const float*)d_in[11];
    const float* b2    = (const float*)d_in[12];
    const float* W_red = (const float*)d_in[13];
    const float* g3    = (const float*)d_in[14];
    const float* b3    = (const float*)d_in[15];
    float* out = (float*)d_out;

    cudaFuncSetAttribute(k_dla0, cudaFuncAttributeMaxDynamicSharedMemorySize, 24 * 340 * 4);
    cudaFuncSetAttribute(k_av, cudaFuncAttributeMaxDynamicSharedMemorySize, 65536);
    cudaFuncSetAttribute(k_out, cudaFuncAttributeMaxDynamicSharedMemorySize, 256 * 36 * 4);

    k_all_proj<<<dim3(16, 48), 256>>>(q, Wq, kv, Wkv);          // 0
    k_attn<<<dim3(128, 16), 256>>>(rpb);                        // 1
    k_gram<<<dim3(16, 32), 256>>>();                            // 2
    k_dla0<<<dim3(8, 128, 16), 256, 24 * 340 * 4>>>(W_exp, g1, b1, W_dw);  // 3 <- ncu capture slot
    k_red<<<dim3(16, 128), 256>>>(g2, b2, W_red);               // 4
    k_av<<<dim3(128, 32), 256, 65536>>>(g3, b3);                // 5
    k_out<<<dim3(16, 32), 256, 256 * 36 * 4>>>(Wp, bp, out);    // 6
}

// round 14
// speedup vs baseline: 1.2688x; 1.0368x over previous
#include <cuda_runtime.h>
#include <math.h>

#define B_   16
#define C_   256
#define NH_  8
#define HD_  32
#define N_   1024
#define M_   256
#define HID_ 24
#define EPS_ 1e-5f

// ---------------- scratch ----------------
__device__ float S_q[B_ * NH_ * N_ * HD_];
__device__ float S_k[B_ * NH_ * M_ * HD_];
__device__ float S_v[B_ * NH_ * M_ * HD_];
__device__ float S_attn[B_ * NH_ * N_ * M_];   // 134 MB
__device__ float S_y[B_ * HID_ * N_ * M_];     // 403 MB
__device__ float S_r[B_ * NH_ * N_ * M_];      // 134 MB
__device__ float S_hout[B_ * N_ * C_];
__device__ float S_gram[B_ * 36];
__device__ float S_stats2[B_ * 3 * 2];
__device__ float S_stats3[B_ * 2];

__device__ __forceinline__ float wred(float v) {
#pragma unroll
    for (int o = 16; o; o >>= 1) v += __shfl_xor_sync(0xffffffffu, v, o);
    return v;
}
__device__ __forceinline__ float tanh_fast(float x) {
    float y;
    asm("tanh.approx.f32 %0, %1;" : "=f"(y) : "f"(x));
    return y;
}
__device__ __forceinline__ float fswish(float x) {
    return 0.5f * x * (1.f + tanh_fast(0.5f * x));
}

// ---------------- fused projections (q + kv) + scratch zeroing ----------------
__global__ __launch_bounds__(256) void k_all_proj(
    const float* __restrict__ q, const float* __restrict__ Wq,
    const float* __restrict__ kv, const float* __restrict__ Wkv) {
    __shared__ float sbuf[8192];
    const int b = blockIdx.x;
    const int y = blockIdx.y;
    const int t = threadIdx.x;
    if (b == 0 && y == 0) {
        for (int i = t; i < 576; i += 256) S_gram[i] = 0.f;
        if (t < 96) S_stats2[t] = 0.f;
        if (t < 32) S_stats3[t] = 0.f;
    }
    if (y < 32) {
        const int n0 = y * 32;
        for (int idx = t; idx < 2048; idx += 256) {
            int c = idx >> 3, i4 = idx & 7;
            ((float4*)sbuf)[idx] = ((const float4*)(q + (b * 256 + c) * 1024 + n0))[i4];
        }
        __syncthreads();
        float acc[32];
#pragma unroll
        for (int i = 0; i < 32; i++) acc[i] = 0.f;
        const float* wrow = Wq + t * 256;
        for (int c = 0; c < 256; c++) {
            float w = __ldg(wrow + c);
            const float4* q4 = (const float4*)(sbuf + c * 32);
#pragma unroll
            for (int i4 = 0; i4 < 8; i4++) {
                float4 qq = q4[i4];
                acc[i4 * 4 + 0] += qq.x * w;
                acc[i4 * 4 + 1] += qq.y * w;
                acc[i4 * 4 + 2] += qq.z * w;
                acc[i4 * 4 + 3] += qq.w * w;
            }
        }
        int h = t >> 5, d = t & 31;
#pragma unroll
        for (int i = 0; i < 32; i++)
            S_q[((b * 8 + h) * 1024 + n0 + i) * 32 + d] = acc[i];
    } else {
        const int m0 = (y - 32) * 16;
        for (int idx = t; idx < 4096; idx += 256) {
            int c = idx >> 4, i = idx & 15;
            sbuf[c * 16 + i] = kv[(b * 256 + c) * 256 + m0 + i];
        }
        __syncthreads();
        for (int jj = 0; jj < 2; jj++) {
            int j = t + jj * 256;
            float acc[16];
#pragma unroll
            for (int i = 0; i < 16; i++) acc[i] = 0.f;
            const float* wrow = Wkv + j * 256;
            for (int c = 0; c < 256; c++) {
                float w = __ldg(wrow + c);
                const float4* k4 = (const float4*)(sbuf + c * 16);
#pragma unroll
                for (int i4 = 0; i4 < 4; i4++) {
                    float4 kk = k4[i4];
                    acc[i4 * 4 + 0] += kk.x * w;
                    acc[i4 * 4 + 1] += kk.y * w;
                    acc[i4 * 4 + 2] += kk.z * w;
                    acc[i4 * 4 + 3] += kk.w * w;
                }
            }
            float* dst = (j < 256) ? S_k : S_v;
            int hd = j & 255;
            int h = hd >> 5, d = hd & 31;
#pragma unroll
            for (int i = 0; i < 16; i++)
                dst[((b * 8 + h) * 256 + m0 + i) * 32 + d] = acc[i];
        }
    }
}

// ---------------- attention: register-tiled QK^T + softmax (fp32) ----------------
__global__ __launch_bounds__(256) void k_attn(const float* __restrict__ rpb) {
    const int bh = blockIdx.x;
    const int n0 = blockIdx.y * 64;
    __shared__ float Qs[32 * 68];
    __shared__ float Ks[32 * 260];
    const int t = threadIdx.x;
    {
        const int d = t & 31, g = t >> 5;
        const float* qsrc = S_q + (size_t)(bh * 1024 + n0) * 32 + d;
#pragma unroll
        for (int i = 0; i < 8; i++)
            Qs[d * 68 + g * 8 + i] = qsrc[(g * 8 + i) * 32];
        const float* ksrc = S_k + (size_t)bh * 8192 + d;
#pragma unroll
        for (int i = 0; i < 32; i++)
            Ks[d * 260 + g * 32 + i] = ksrc[(g * 32 + i) * 32];
    }
    __syncthreads();
    const int mg = t & 31;
    const int ng = t >> 5;
    float acc[8][8];
#pragma unroll
    for (int i = 0; i < 8; i++)
#pragma unroll
        for (int j = 0; j < 8; j++) acc[i][j] = 0.f;
#pragma unroll 4
    for (int k = 0; k < 32; k++) {
        float4 q0 = *(const float4*)&Qs[k * 68 + ng * 8];
        float4 q1 = *(const float4*)&Qs[k * 68 + ng * 8 + 4];
        float4 k0 = *(const float4*)&Ks[k * 260 + mg * 8];
        float4 k1 = *(const float4*)&Ks[k * 260 + mg * 8 + 4];
        float qv[8] = {q0.x, q0.y, q0.z, q0.w, q1.x, q1.y, q1.z, q1.w};
        float kw[8] = {k0.x, k0.y, k0.z, k0.w, k1.x, k1.y, k1.z, k1.w};
#pragma unroll
        for (int i = 0; i < 8; i++)
#pragma unroll
            for (int j = 0; j < 8; j++) acc[i][j] += qv[i] * kw[j];
    }
    const float scale = 0.17677669529663689f;
#pragma unroll
    for (int i = 0; i < 8; i++) {
        const int n = n0 + ng * 8 + i;
        const float* rp = rpb + (size_t)n * 256 + mg * 8;
        float4 r0 = *(const float4*)rp;
        float4 r1 = *(const float4*)(rp + 4);
        float rb[8] = {r0.x, r0.y, r0.z, r0.w, r1.x, r1.y, r1.z, r1.w};
        float mx = -1e30f;
#pragma unroll
        for (int j = 0; j < 8; j++) {
            acc[i][j] = acc[i][j] * scale + rb[j];
            mx = fmaxf(mx, acc[i][j]);
        }
#pragma unroll
        for (int o = 16; o; o >>= 1) mx = fmaxf(mx, __shfl_xor_sync(0xffffffffu, mx, o));
        float s = 0.f;
#pragma unroll
        for (int j = 0; j < 8; j++) {
            float e = __expf(acc[i][j] - mx);
            acc[i][j] = e;
            s += e;
        }
        s = wred(s);
        float inv = __fdividef(1.f, s);
        float* dst = S_attn + (size_t)(bh * 1024 + n) * 256 + mg * 8;
        float4 o0 = make_float4(acc[i][0] * inv, acc[i][1] * inv, acc[i][2] * inv, acc[i][3] * inv);
        float4 o1 = make_float4(acc[i][4] * inv, acc[i][5] * inv, acc[i][6] * inv, acc[i][7] * inv);
        *(float4*)dst = o0;
        *(float4*)(dst + 4) = o1;
    }
}

// ---------------- head Gram matrix ----------------
__global__ __launch_bounds__(256) void k_gram() {
    const int b = blockIdx.x;
    const int base = blockIdx.y * 8192 + threadIdx.x;
    __shared__ float gs[36];
    const int t = threadIdx.x;
    if (t < 36) gs[t] = 0.f;
    __syncthreads();
    float g[36];
#pragma unroll
    for (int c = 0; c < 36; c++) g[c] = 0.f;
    const float* A = S_attn + (size_t)b * 2097152;
#pragma unroll 1
    for (int k = 0; k < 32; k++) {
        int pix = base + k * 256;
        float a[8];
#pragma unroll
        for (int h = 0; h < 8; h++) a[h] = A[h * 262144 + pix];
        int c = 0;
#pragma unroll
        for (int i = 0; i < 8; i++)
#pragma unroll
            for (int j = i; j < 8; j++) g[c++] += a[i] * a[j];
    }
#pragma unroll
    for (int c = 0; c < 36; c++) {
        g[c] = wred(g[c]);
        if ((t & 31) == 0) atomicAdd(&gs[c], g[c]);
    }
    __syncthreads();
    if (t < 36) atomicAdd(&S_gram[b * 36 + t], gs[t]);
}

// ---------------- DLA pass 0: stats-from-gram + expand+GN1+swish+dw3x3 ----------------
// xact layout: 24 channels x 10 rows x stride 36 (halo cols 0..33 = global m0-1..m0+32)
__global__ __launch_bounds__(256, 4) void k_dla0(
    const float* __restrict__ W_exp, const float* __restrict__ g1,
    const float* __restrict__ b1, const float* __restrict__ W_dw) {
    const int m0 = blockIdx.x * 32;
    const int n0 = blockIdx.y * 8;      // 8-row core tile
    const int b = blockIdx.z;
    extern __shared__ float xact[];     // 24 * 360 floats = 34560 B
    __shared__ float we[192], wd[216];
    __shared__ float g1s[24], b1s[24];
    __shared__ float Gs[36];
    __shared__ float osum[24], osq[24];
    __shared__ float mu1[3], rs1[3];
    __shared__ float red[6];
    const int t = threadIdx.x;
    if (t < 192) we[t] = W_exp[t];
    if (t < 216) wd[t] = W_dw[t];
    if (t < 24) { g1s[t] = g1[t]; b1s[t] = b1[t]; }
    if (t < 36) Gs[t] = S_gram[b * 36 + t];
    if (t < 6) red[t] = 0.f;
    __syncthreads();
    // GN1 stats analytically from Gram
    if (t < 24) {
        const int o = t;
        float wo[8];
#pragma unroll
        for (int h = 0; h < 8; h++) wo[h] = we[o * 8 + h];
        float sw = 0.f;
#pragma unroll
        for (int h = 0; h < 8; h++) sw += wo[h];
        float sxx = 0.f;
#pragma unroll
        for (int i = 0; i < 8; i++)
#pragma unroll
            for (int j = 0; j < 8; j++) {
                int a = i < j ? i : j, bb = i < j ? j : i;
                sxx += wo[i] * wo[j] * Gs[8 * a - a * (a - 1) / 2 + (bb - a)];
            }
        osum[t] = sw;
        osq[t] = sxx;
    }
    __syncthreads();
    if (t < 3) {
        float sw = 0.f, sxx = 0.f;
#pragma unroll
        for (int k = 0; k < 8; k++) { sw += osum[t * 8 + k]; sxx += osq[t * 8 + k]; }
        float m = sw * (1024.f / 2097152.f);
        mu1[t] = m;
        rs1[t] = rsqrtf(sxx * (1.f / 2097152.f) - m * m + EPS_);
    }
    __syncthreads();

    // Phase 1: activated expand tile with halo (10 x 34 entries, stride 36)
    const float* Ab = S_attn + (size_t)b * 2097152;
#pragma unroll 1
    for (int idx = t; idx < 340; idx += 256) {
        int i = idx / 34, j = idx - i * 34;
        int gi = n0 - 1 + i, gj = m0 - 1 + j;
        int sidx = i * 36 + j;
        if ((unsigned)gi < 1024u && (unsigned)gj < 256u) {
            const float* A = Ab + gi * 256 + gj;
            float a[8];
#pragma unroll
            for (int h = 0; h < 8; h++) a[h] = A[h * 262144];
#pragma unroll
            for (int o = 0; o < 24; o++) {
                float x = 0.f;
#pragma unroll
                for (int h = 0; h < 8; h++) x += we[o * 8 + h] * a[h];
                int g = o >> 3;
                x = (x - mu1[g]) * rs1[g] * g1s[o] + b1s[o];
                xact[o * 360 + sidx] = fswish(x);
            }
        } else {
#pragma unroll
            for (int o = 0; o < 24; o++) xact[o * 360 + sidx] = 0.f;
        }
    }
    __syncthreads();

    // Phase 2: dwconv over 8x32 core, 2-pixel pairs, float2 smem loads (no duplication)
    {
        const int half = t >> 7;        // 0: ch 0-11, 1: ch 12-23
        const int pl = t & 127;
        const int i = pl >> 4;          // row 0..7
        const int p = pl & 15;          // pair 0..15 -> core cols 2p, 2p+1
        const int ob = half * 12;
        size_t gp = (size_t)(n0 + i) * 256 + (m0 + 2 * p);
        float sA = 0, qA = 0, sB = 0, qB = 0;
#pragma unroll 4
        for (int c = 0; c < 12; c++) {
            const int o = ob + c;
            const float* xb = xact + o * 360 + i * 36 + 2 * p;
            const float* w = wd + o * 9;
            float2 a0 = *(const float2*)(xb);
            float2 b0 = *(const float2*)(xb + 2);
            float2 a1 = *(const float2*)(xb + 36);
            float2 b1 = *(const float2*)(xb + 38);
            float2 a2 = *(const float2*)(xb + 72);
            float2 b2 = *(const float2*)(xb + 74);
            float y0 = w[0] * a0.x + w[1] * a0.y + w[2] * b0.x
                     + w[3] * a1.x + w[4] * a1.y + w[5] * b1.x
                     + w[6] * a2.x + w[7] * a2.y + w[8] * b2.x;
            float y1 = w[0] * a0.y + w[1] * b0.x + w[2] * b0.y
                     + w[3] * a1.y + w[4] * b1.x + w[5] * b1.y
                     + w[6] * a2.y + w[7] * b2.x + w[8] * b2.y;
            *(float2*)&S_y[((size_t)(b * 24 + o)) * 262144 + gp] = make_float2(y0, y1);
            float sv = y0 + y1, qv = y0 * y0 + y1 * y1;
            bool first = (half == 0) ? (c < 8) : (c < 4);
            if (first) { sA += sv; qA += qv; }
            else       { sB += sv; qB += qv; }
        }
        sA = wred(sA); qA = wred(qA); sB = wred(sB); qB = wred(qB);
        if ((t & 31) == 0) {
            if (half == 0) {
                atomicAdd(&red[0], sA); atomicAdd(&red[1], qA);
                atomicAdd(&red[2], sB); atomicAdd(&red[3], qB);
            } else {
                atomicAdd(&red[2], sA); atomicAdd(&red[3], qA);
                atomicAdd(&red[4], sB); atomicAdd(&red[5], qB);
            }
        }
    }
    __syncthreads();
    if (t < 6) atomicAdd(&S_stats2[b * 6 + t], red[t]);
}

// ---------------- DLA pass 1: GN2->swish->1x1 reduce -> r + GN3 stats ----------------
__global__ __launch_bounds__(256) void k_red(
    const float* __restrict__ g2, const float* __restrict__ b2,
    const float* __restrict__ W_red) {
    const int b = blockIdx.x;
    const int pix0 = blockIdx.y * 2048;
    __shared__ float wrd[192], g2s[24], b2s[24];
    __shared__ float mu2[3], rs2[3];
    __shared__ float red[2];
    const int t = threadIdx.x;
    if (t < 192) wrd[t] = W_red[t];
    if (t < 24) { g2s[t] = g2[t]; b2s[t] = b2[t]; }
    if (t < 3) {
        const float cnt = 2097152.f;
        float s = S_stats2[b * 6 + 2 * t], qq = S_stats2[b * 6 + 2 * t + 1];
        float m = s / cnt;
        mu2[t] = m;
        rs2[t] = rsqrtf(qq / cnt - m * m + EPS_);
    }
    if (t < 2) red[t] = 0.f;
    __syncthreads();
    float s3 = 0, q3 = 0;
    const float* Y = S_y + (size_t)b * 24 * 262144;
    float* R = S_r + (size_t)b * 8 * 262144;
#pragma unroll 1
    for (int k = 0; k < 8; k++) {
        int pix = pix0 + k * 256 + t;
        float r[8];
#pragma unroll
        for (int h = 0; h < 8; h++) r[h] = 0.f;
#pragma unroll
        for (int o = 0; o < 24; o++) {
            float y = Y[(size_t)o * 262144 + pix];
            int g = o >> 3;
            float z = (y - mu2[g]) * rs2[g] * g2s[o] + b2s[o];
            z = fswish(z);
#pragma unroll
            for (int h = 0; h < 8; h++) r[h] += wrd[h * 24 + o] * z;
        }
#pragma unroll
        for (int h = 0; h < 8; h++) {
            R[(size_t)h * 262144 + pix] = r[h];
            s3 += r[h];
            q3 += r[h] * r[h];
        }
    }
    s3 = wred(s3); q3 = wred(q3);
    if ((t & 31) == 0) { atomicAdd(&red[0], s3); atomicAdd(&red[1], q3); }
    __syncthreads();
    if (t < 2) atomicAdd(&S_stats3[b * 2 + t], red[t]);
}

// ---------------- AV product (GN3 applied on the fly) ----------------
__global__ __launch_bounds__(256) void k_av(const float* __restrict__ g3, const float* __restrict__ b3) {
    const int bh = blockIdx.x;
    const int n0 = blockIdx.y * 32;
    const int b = bh >> 3, h = bh & 7;
    extern __shared__ float sm[];
    float* vs = sm;          // 8192
    float* rs = sm + 8192;   // 8192
    __shared__ float params[2];
    if (threadIdx.x == 0) {
        const float cnt = 2097152.f;
        float s = S_stats3[b * 2], qq = S_stats3[b * 2 + 1];
        float m = s / cnt;
        float rstd = rsqrtf(qq / cnt - m * m + EPS_);
        float gh = g3[h];
        params[0] = rstd * gh;
        params[1] = b3[h] - m * rstd * gh;
    }
    __syncthreads();
    float scl = params[0], sft = params[1];
    for (int idx = threadIdx.x; idx < 8192; idx += 256)
        vs[idx] = S_v[(size_t)bh * 8192 + idx];
    const float* R = S_r + (size_t)(bh * 1024 + n0) * 256;
    for (int idx = threadIdx.x; idx < 8192; idx += 256)
        rs[idx] = R[idx] * scl + sft;
    __syncthreads();
    const int d = threadIdx.x & 31, nb = threadIdx.x >> 5;
    float acc[4];
#pragma unroll
    for (int k = 0; k < 4; k++) acc[k] = 0.f;
    for (int m = 0; m < 256; m += 4) {
        float v0 = vs[m * 32 + d];
        float v1 = vs[(m + 1) * 32 + d];
        float v2 = vs[(m + 2) * 32 + d];
        float v3 = vs[(m + 3) * 32 + d];
#pragma unroll
        for (int k = 0; k < 4; k++) {
            int nl = nb + k * 8;
            float4 rr = *(const float4*)(rs + nl * 256 + m);
            acc[k] += rr.x * v0 + rr.y * v1 + rr.z * v2 + rr.w * v3;
        }
    }
#pragma unroll
    for (int k = 0; k < 4; k++) {
        int nl = nb + k * 8;
        S_hout[(size_t)(b * 1024 + n0 + nl) * 256 + h * 32 + d] = acc[k];
    }
}

// ---------------- output projection + NCHW transpose ----------------
__global__ __launch_bounds__(256) void k_out(const float* __restrict__ Wp, const float* __restrict__ bp,
                                             float* __restrict__ out) {
    const int b = blockIdx.x;
    const int n0 = blockIdx.y * 32;
    extern __shared__ float sm2[];
    float* hs = sm2;
    for (int idx = threadIdx.x; idx < 8192; idx += 256) {
        int nl = idx >> 8, cp = idx & 255;
        hs[cp * 36 + nl] = S_hout[(size_t)(b * 1024 + n0 + nl) * 256 + cp];
    }
    __syncthreads();
    int c = threadIdx.x;
    float acc[32];
#pragma unroll
    for (int i = 0; i < 32; i++) acc[i] = 0.f;
    const float* wrow = Wp + c * 256;
    for (int cp = 0; cp < 256; cp++) {
        float w = __ldg(wrow + cp);
        const float4* h4 = (const float4*)(hs + cp * 36);
#pragma unroll
        for (int i4 = 0; i4 < 8; i4++) {
            float4 hh = h4[i4];
            acc[i4 * 4 + 0] += hh.x * w;
            acc[i4 * 4 + 1] += hh.y * w;
            acc[i4 * 4 + 2] += hh.z * w;
            acc[i4 * 4 + 3] += hh.w * w;
        }
    }
    float bpc = bp[c];
    __syncthreads();
    float* os = sm2;
#pragma unroll
    for (int i = 0; i < 32; i++) os[c * 36 + i] = acc[i] + bpc;
    __syncthreads();
    for (int idx = threadIdx.x; idx < 8192; idx += 256) {
        int c2 = idx >> 5, i2 = idx & 31;
        out[((size_t)b * 256 + c2) * 1024 + n0 + i2] = os[c2 * 36 + i2];
    }
}

// ---------------- host launcher ----------------
extern "C" void kernel_launch(void* const* d_in, const int* in_sizes, int n_in,
                              void* d_out, int out_size) {
    const float* q     = (const float*)d_in[0];
    const float* kv    = (const float*)d_in[1];
    const float* Wq    = (const float*)d_in[2];
    const float* Wkv   = (const float*)d_in[3];
    const float* Wp    = (const float*)d_in[4];
    const float* bp    = (const float*)d_in[5];
    const float* rpb   = (const float*)d_in[6];
    const float* W_exp = (const float*)d_in[7];
    const float* g1    = (const float*)d_in[8];
    const float* b1    = (const float*)d_in[9];
    const float* W_dw  = (const float*)d_in[10];
    const float* g2    = (const float*)d_in[11];
    const float* b2    = (const float*)d_in[12];
    const float* W_red = (const float*)d_in[13];
    const float* g3    = (const float*)d_in[14];
    const float* b3    = (const float*)d_in[15];
    float* out = (float*)d_out;

    cudaFuncSetAttribute(k_dla0, cudaFuncAttributeMaxDynamicSharedMemorySize, 24 * 360 * 4);
    cudaFuncSetAttribute(k_av, cudaFuncAttributeMaxDynamicSharedMemorySize, 65536);
    cudaFuncSetAttribute(k_out, cudaFuncAttributeMaxDynamicSharedMemorySize, 256 * 36 * 4);

    k_all_proj<<<dim3(16, 48), 256>>>(q, Wq, kv, Wkv);          // 0
    k_attn<<<dim3(128, 16), 256>>>(rpb);                        // 1
    k_gram<<<dim3(16, 32), 256>>>();                            // 2
    k_dla0<<<dim3(8, 128, 16), 256, 24 * 360 * 4>>>(W_exp, g1, b1, W_dw);  // 3 <- ncu capture slot
    k_red<<<dim3(16, 128), 256>>>(g2, b2, W_red);               // 4
    k_av<<<dim3(128, 32), 256, 65536>>>(g3, b3);                // 5
    k_out<<<dim3(16, 32), 256, 256 * 36 * 4>>>(Wp, bp, out);    // 6
}

// round 15
// speedup vs baseline: 1.4807x; 1.1669x over previous
#include <cuda_runtime.h>
#include <math.h>

#define B_   16
#define C_   256
#define NH_  8
#define HD_  32
#define N_   1024
#define M_   256
#define HID_ 24
#define EPS_ 1e-5f

// ---------------- scratch ----------------
__device__ float S_q[B_ * NH_ * N_ * HD_];
__device__ float S_k[B_ * NH_ * M_ * HD_];
__device__ float S_v[B_ * NH_ * M_ * HD_];
__device__ float S_attn[B_ * NH_ * N_ * M_];   // 134 MB
__device__ float S_y[B_ * HID_ * N_ * M_];     // 403 MB
__device__ float S_r[B_ * NH_ * N_ * M_];      // 134 MB
__device__ float S_hout[B_ * N_ * C_];
__device__ float S_gram[B_ * 36];
__device__ float S_stats2[B_ * 3 * 2];
__device__ float S_stats3[B_ * 2];

__device__ __forceinline__ float wred(float v) {
#pragma unroll
    for (int o = 16; o; o >>= 1) v += __shfl_xor_sync(0xffffffffu, v, o);
    return v;
}
__device__ __forceinline__ float tanh_fast(float x) {
    float y;
    asm("tanh.approx.f32 %0, %1;" : "=f"(y) : "f"(x));
    return y;
}
__device__ __forceinline__ float fswish(float x) {
    return 0.5f * x * (1.f + tanh_fast(0.5f * x));
}

// ---------------- fused projections (q + kv) + scratch zeroing ----------------
__global__ __launch_bounds__(256) void k_all_proj(
    const float* __restrict__ q, const float* __restrict__ Wq,
    const float* __restrict__ kv, const float* __restrict__ Wkv) {
    __shared__ float sbuf[8192];
    const int b = blockIdx.x;
    const int y = blockIdx.y;
    const int t = threadIdx.x;
    if (b == 0 && y == 0) {
        for (int i = t; i < 576; i += 256) S_gram[i] = 0.f;
        if (t < 96) S_stats2[t] = 0.f;
        if (t < 32) S_stats3[t] = 0.f;
    }
    if (y < 32) {
        const int n0 = y * 32;
        for (int idx = t; idx < 2048; idx += 256) {
            int c = idx >> 3, i4 = idx & 7;
            ((float4*)sbuf)[idx] = ((const float4*)(q + (b * 256 + c) * 1024 + n0))[i4];
        }
        __syncthreads();
        float acc[32];
#pragma unroll
        for (int i = 0; i < 32; i++) acc[i] = 0.f;
        const float* wrow = Wq + t * 256;
        for (int c = 0; c < 256; c++) {
            float w = __ldg(wrow + c);
            const float4* q4 = (const float4*)(sbuf + c * 32);
#pragma unroll
            for (int i4 = 0; i4 < 8; i4++) {
                float4 qq = q4[i4];
                acc[i4 * 4 + 0] += qq.x * w;
                acc[i4 * 4 + 1] += qq.y * w;
                acc[i4 * 4 + 2] += qq.z * w;
                acc[i4 * 4 + 3] += qq.w * w;
            }
        }
        int h = t >> 5, d = t & 31;
#pragma unroll
        for (int i = 0; i < 32; i++)
            S_q[((b * 8 + h) * 1024 + n0 + i) * 32 + d] = acc[i];
    } else {
        const int m0 = (y - 32) * 16;
        for (int idx = t; idx < 4096; idx += 256) {
            int c = idx >> 4, i = idx & 15;
            sbuf[c * 16 + i] = kv[(b * 256 + c) * 256 + m0 + i];
        }
        __syncthreads();
        for (int jj = 0; jj < 2; jj++) {
            int j = t + jj * 256;
            float acc[16];
#pragma unroll
            for (int i = 0; i < 16; i++) acc[i] = 0.f;
            const float* wrow = Wkv + j * 256;
            for (int c = 0; c < 256; c++) {
                float w = __ldg(wrow + c);
                const float4* k4 = (const float4*)(sbuf + c * 16);
#pragma unroll
                for (int i4 = 0; i4 < 4; i4++) {
                    float4 kk = k4[i4];
                    acc[i4 * 4 + 0] += kk.x * w;
                    acc[i4 * 4 + 1] += kk.y * w;
                    acc[i4 * 4 + 2] += kk.z * w;
                    acc[i4 * 4 + 3] += kk.w * w;
                }
            }
            float* dst = (j < 256) ? S_k : S_v;
            int hd = j & 255;
            int h = hd >> 5, d = hd & 31;
#pragma unroll
            for (int i = 0; i < 16; i++)
                dst[((b * 8 + h) * 256 + m0 + i) * 32 + d] = acc[i];
        }
    }
}

// ---------------- attention: register-tiled QK^T + softmax (fp32) ----------------
__global__ __launch_bounds__(256) void k_attn(const float* __restrict__ rpb) {
    const int bh = blockIdx.x;
    const int n0 = blockIdx.y * 64;
    __shared__ float Qs[32 * 68];
    __shared__ float Ks[32 * 260];
    const int t = threadIdx.x;
    {
        const int d = t & 31, g = t >> 5;
        const float* qsrc = S_q + (size_t)(bh * 1024 + n0) * 32 + d;
#pragma unroll
        for (int i = 0; i < 8; i++)
            Qs[d * 68 + g * 8 + i] = qsrc[(g * 8 + i) * 32];
        const float* ksrc = S_k + (size_t)bh * 8192 + d;
#pragma unroll
        for (int i = 0; i < 32; i++)
            Ks[d * 260 + g * 32 + i] = ksrc[(g * 32 + i) * 32];
    }
    __syncthreads();
    const int mg = t & 31;
    const int ng = t >> 5;
    float acc[8][8];
#pragma unroll
    for (int i = 0; i < 8; i++)
#pragma unroll
        for (int j = 0; j < 8; j++) acc[i][j] = 0.f;
#pragma unroll 4
    for (int k = 0; k < 32; k++) {
        float4 q0 = *(const float4*)&Qs[k * 68 + ng * 8];
        float4 q1 = *(const float4*)&Qs[k * 68 + ng * 8 + 4];
        float4 k0 = *(const float4*)&Ks[k * 260 + mg * 8];
        float4 k1 = *(const float4*)&Ks[k * 260 + mg * 8 + 4];
        float qv[8] = {q0.x, q0.y, q0.z, q0.w, q1.x, q1.y, q1.z, q1.w};
        float kw[8] = {k0.x, k0.y, k0.z, k0.w, k1.x, k1.y, k1.z, k1.w};
#pragma unroll
        for (int i = 0; i < 8; i++)
#pragma unroll
            for (int j = 0; j < 8; j++) acc[i][j] += qv[i] * kw[j];
    }
    const float scale = 0.17677669529663689f;
#pragma unroll
    for (int i = 0; i < 8; i++) {
        const int n = n0 + ng * 8 + i;
        const float* rp = rpb + (size_t)n * 256 + mg * 8;
        float4 r0 = *(const float4*)rp;
        float4 r1 = *(const float4*)(rp + 4);
        float rb[8] = {r0.x, r0.y, r0.z, r0.w, r1.x, r1.y, r1.z, r1.w};
        float mx = -1e30f;
#pragma unroll
        for (int j = 0; j < 8; j++) {
            acc[i][j] = acc[i][j] * scale + rb[j];
            mx = fmaxf(mx, acc[i][j]);
        }
#pragma unroll
        for (int o = 16; o; o >>= 1) mx = fmaxf(mx, __shfl_xor_sync(0xffffffffu, mx, o));
        float s = 0.f;
#pragma unroll
        for (int j = 0; j < 8; j++) {
            float e = __expf(acc[i][j] - mx);
            acc[i][j] = e;
            s += e;
        }
        s = wred(s);
        float inv = __fdividef(1.f, s);
        float* dst = S_attn + (size_t)(bh * 1024 + n) * 256 + mg * 8;
        float4 o0 = make_float4(acc[i][0] * inv, acc[i][1] * inv, acc[i][2] * inv, acc[i][3] * inv);
        float4 o1 = make_float4(acc[i][4] * inv, acc[i][5] * inv, acc[i][6] * inv, acc[i][7] * inv);
        *(float4*)dst = o0;
        *(float4*)(dst + 4) = o1;
    }
}

// ---------------- head Gram matrix ----------------
__global__ __launch_bounds__(256) void k_gram() {
    const int b = blockIdx.x;
    const int base = blockIdx.y * 8192 + threadIdx.x;
    __shared__ float gs[36];
    const int t = threadIdx.x;
    if (t < 36) gs[t] = 0.f;
    __syncthreads();
    float g[36];
#pragma unroll
    for (int c = 0; c < 36; c++) g[c] = 0.f;
    const float* A = S_attn + (size_t)b * 2097152;
#pragma unroll 1
    for (int k = 0; k < 32; k++) {
        int pix = base + k * 256;
        float a[8];
#pragma unroll
        for (int h = 0; h < 8; h++) a[h] = A[h * 262144 + pix];
        int c = 0;
#pragma unroll
        for (int i = 0; i < 8; i++)
#pragma unroll
            for (int j = i; j < 8; j++) g[c++] += a[i] * a[j];
    }
#pragma unroll
    for (int c = 0; c < 36; c++) {
        g[c] = wred(g[c]);
        if ((t & 31) == 0) atomicAdd(&gs[c], g[c]);
    }
    __syncthreads();
    if (t < 36) atomicAdd(&S_gram[b * 36 + t], gs[t]);
}

// ---------------- DLA pass 0: stats-from-gram + expand+GN1+swish+dw3x3 ----------------
// xact layout: 24 channels x 10 rows x stride 36 (halo cols 0..33 = global m0-1..m0+32)
__global__ __launch_bounds__(256, 4) void k_dla0(
    const float* __restrict__ W_exp, const float* __restrict__ g1,
    const float* __restrict__ b1, const float* __restrict__ W_dw) {
    const int m0 = blockIdx.x * 32;
    const int n0 = blockIdx.y * 8;      // 8-row core tile
    const int b = blockIdx.z;
    extern __shared__ float xact[];     // 24 * 360 floats = 34560 B
    __shared__ float we[192], wd[216];
    __shared__ float g1s[24], b1s[24];
    __shared__ float Gs[36];
    __shared__ float osum[24], osq[24];
    __shared__ float mu1[3], rs1[3];
    __shared__ float red[6];
    const int t = threadIdx.x;
    if (t < 192) we[t] = W_exp[t];
    if (t < 216) wd[t] = W_dw[t];
    if (t < 24) { g1s[t] = g1[t]; b1s[t] = b1[t]; }
    if (t < 36) Gs[t] = S_gram[b * 36 + t];
    if (t < 6) red[t] = 0.f;
    __syncthreads();
    // GN1 stats analytically from Gram
    if (t < 24) {
        const int o = t;
        float wo[8];
#pragma unroll
        for (int h = 0; h < 8; h++) wo[h] = we[o * 8 + h];
        float sw = 0.f;
#pragma unroll
        for (int h = 0; h < 8; h++) sw += wo[h];
        float sxx = 0.f;
#pragma unroll
        for (int i = 0; i < 8; i++)
#pragma unroll
            for (int j = 0; j < 8; j++) {
                int a = i < j ? i : j, bb = i < j ? j : i;
                sxx += wo[i] * wo[j] * Gs[8 * a - a * (a - 1) / 2 + (bb - a)];
            }
        osum[t] = sw;
        osq[t] = sxx;
    }
    __syncthreads();
    if (t < 3) {
        float sw = 0.f, sxx = 0.f;
#pragma unroll
        for (int k = 0; k < 8; k++) { sw += osum[t * 8 + k]; sxx += osq[t * 8 + k]; }
        float m = sw * (1024.f / 2097152.f);
        mu1[t] = m;
        rs1[t] = rsqrtf(sxx * (1.f / 2097152.f) - m * m + EPS_);
    }
    __syncthreads();

    // Phase 1: activated expand tile with halo, 2-pixel pairs, float2 STS
    // 10 rows x 17 pairs (34 halo cols) = 170 work items
    const float* Ab = S_attn + (size_t)b * 2097152;
#pragma unroll 1
    for (int pp = t; pp < 170; pp += 256) {
        int row = pp / 17;
        int jp = (pp - row * 17) * 2;      // even halo col 0..32
        int gi = n0 - 1 + row;
        int gj = m0 - 1 + jp;              // global col of first elem (odd)
        int sidx = row * 36 + jp;
        bool vrow = (unsigned)gi < 1024u;
        bool v0 = vrow && ((unsigned)gj < 256u);
        bool v1 = vrow && ((unsigned)(gj + 1) < 256u);
        const float* A = Ab + gi * 256 + gj;
        float a0[8], a1[8];
#pragma unroll
        for (int h = 0; h < 8; h++) {
            a0[h] = v0 ? A[h * 262144] : 0.f;
            a1[h] = v1 ? A[h * 262144 + 1] : 0.f;
        }
#pragma unroll
        for (int o = 0; o < 24; o++) {
            float x0 = 0.f, x1 = 0.f;
#pragma unroll
            for (int h = 0; h < 8; h++) {
                float w = we[o * 8 + h];
                x0 += w * a0[h];
                x1 += w * a1[h];
            }
            int g = o >> 3;
            float S = rs1[g] * g1s[o];
            float T = b1s[o] - mu1[g] * S;
            x0 = x0 * S + T;
            x1 = x1 * S + T;
            x0 = v0 ? fswish(x0) : 0.f;
            x1 = v1 ? fswish(x1) : 0.f;
            *(float2*)&xact[o * 360 + sidx] = make_float2(x0, x1);
        }
    }
    __syncthreads();

    // Phase 2: dwconv over 8x32 core, 2-pixel pairs, float2 smem loads (no duplication)
    {
        const int half = t >> 7;        // 0: ch 0-11, 1: ch 12-23
        const int pl = t & 127;
        const int i = pl >> 4;          // row 0..7
        const int p = pl & 15;          // pair 0..15 -> core cols 2p, 2p+1
        const int ob = half * 12;
        size_t gp = (size_t)(n0 + i) * 256 + (m0 + 2 * p);
        float sA = 0, qA = 0, sB = 0, qB = 0;
#pragma unroll 4
        for (int c = 0; c < 12; c++) {
            const int o = ob + c;
            const float* xb = xact + o * 360 + i * 36 + 2 * p;
            const float* w = wd + o * 9;
            float2 a0 = *(const float2*)(xb);
            float2 b0 = *(const float2*)(xb + 2);
            float2 a1 = *(const float2*)(xb + 36);
            float2 b1 = *(const float2*)(xb + 38);
            float2 a2 = *(const float2*)(xb + 72);
            float2 b2 = *(const float2*)(xb + 74);
            float y0 = w[0] * a0.x + w[1] * a0.y + w[2] * b0.x
                     + w[3] * a1.x + w[4] * a1.y + w[5] * b1.x
                     + w[6] * a2.x + w[7] * a2.y + w[8] * b2.x;
            float y1 = w[0] * a0.y + w[1] * b0.x + w[2] * b0.y
                     + w[3] * a1.y + w[4] * b1.x + w[5] * b1.y
                     + w[6] * a2.y + w[7] * b2.x + w[8] * b2.y;
            *(float2*)&S_y[((size_t)(b * 24 + o)) * 262144 + gp] = make_float2(y0, y1);
            float sv = y0 + y1, qv = y0 * y0 + y1 * y1;
            bool first = (half == 0) ? (c < 8) : (c < 4);
            if (first) { sA += sv; qA += qv; }
            else       { sB += sv; qB += qv; }
        }
        sA = wred(sA); qA = wred(qA); sB = wred(sB); qB = wred(qB);
        if ((t & 31) == 0) {
            if (half == 0) {
                atomicAdd(&red[0], sA); atomicAdd(&red[1], qA);
                atomicAdd(&red[2], sB); atomicAdd(&red[3], qB);
            } else {
                atomicAdd(&red[2], sA); atomicAdd(&red[3], qA);
                atomicAdd(&red[4], sB); atomicAdd(&red[5], qB);
            }
        }
    }
    __syncthreads();
    if (t < 6) atomicAdd(&S_stats2[b * 6 + t], red[t]);
}

// ---------------- DLA pass 1: GN2->swish->1x1 reduce, pixel pairs (float2 I/O) ----------------
__global__ __launch_bounds__(256) void k_red(
    const float* __restrict__ g2, const float* __restrict__ b2,
    const float* __restrict__ W_red) {
    const int b = blockIdx.x;
    const int p0 = blockIdx.y * 1024;   // pair index; grid.y = 128
    __shared__ float wrd[192], g2s[24], b2s[24];
    __shared__ float mu2[3], rs2[3];
    __shared__ float red[2];
    const int t = threadIdx.x;
    if (t < 192) wrd[t] = W_red[t];
    if (t < 24) { g2s[t] = g2[t]; b2s[t] = b2[t]; }
    if (t < 3) {
        const float cnt = 2097152.f;
        float s = S_stats2[b * 6 + 2 * t], qq = S_stats2[b * 6 + 2 * t + 1];
        float m = s / cnt;
        mu2[t] = m;
        rs2[t] = rsqrtf(qq / cnt - m * m + EPS_);
    }
    if (t < 2) red[t] = 0.f;
    __syncthreads();
    float s3 = 0, q3 = 0;
    const float* Y = S_y + (size_t)b * 24 * 262144;
    float* R = S_r + (size_t)b * 8 * 262144;
#pragma unroll 1
    for (int k = 0; k < 4; k++) {
        int pr = p0 + k * 256 + t;
        float r0[8], r1[8];
#pragma unroll
        for (int h = 0; h < 8; h++) { r0[h] = 0.f; r1[h] = 0.f; }
#pragma unroll
        for (int o = 0; o < 24; o++) {
            float2 yf = ((const float2*)(Y + (size_t)o * 262144))[pr];
            int g = o >> 3;
            float S = rs2[g] * g2s[o];
            float T = b2s[o] - mu2[g] * S;
            float z0 = fswish(yf.x * S + T);
            float z1 = fswish(yf.y * S + T);
#pragma unroll
            for (int h = 0; h < 8; h++) {
                float w = wrd[h * 24 + o];
                r0[h] += w * z0;
                r1[h] += w * z1;
            }
        }
#pragma unroll
        for (int h = 0; h < 8; h++) {
            ((float2*)(R + (size_t)h * 262144))[pr] = make_float2(r0[h], r1[h]);
            s3 += r0[h] + r1[h];
            q3 += r0[h] * r0[h] + r1[h] * r1[h];
        }
    }
    s3 = wred(s3); q3 = wred(q3);
    if ((t & 31) == 0) { atomicAdd(&red[0], s3); atomicAdd(&red[1], q3); }
    __syncthreads();
    if (t < 2) atomicAdd(&S_stats3[b * 2 + t], red[t]);
}

// ---------------- AV product (GN3 applied on the fly) ----------------
__global__ __launch_bounds__(256) void k_av(const float* __restrict__ g3, const float* __restrict__ b3) {
    const int bh = blockIdx.x;
    const int n0 = blockIdx.y * 32;
    const int b = bh >> 3, h = bh & 7;
    extern __shared__ float sm[];
    float* vs = sm;          // 8192
    float* rs = sm + 8192;   // 8192
    __shared__ float params[2];
    if (threadIdx.x == 0) {
        const float cnt = 2097152.f;
        float s = S_stats3[b * 2], qq = S_stats3[b * 2 + 1];
        float m = s / cnt;
        float rstd = rsqrtf(qq / cnt - m * m + EPS_);
        float gh = g3[h];
        params[0] = rstd * gh;
        params[1] = b3[h] - m * rstd * gh;
    }
    __syncthreads();
    float scl = params[0], sft = params[1];
    for (int idx = threadIdx.x; idx < 8192; idx += 256)
        vs[idx] = S_v[(size_t)bh * 8192 + idx];
    const float* R = S_r + (size_t)(bh * 1024 + n0) * 256;
    for (int idx = threadIdx.x; idx < 8192; idx += 256)
        rs[idx] = R[idx] * scl + sft;
    __syncthreads();
    const int d = threadIdx.x & 31, nb = threadIdx.x >> 5;
    float acc[4];
#pragma unroll
    for (int k = 0; k < 4; k++) acc[k] = 0.f;
    for (int m = 0; m < 256; m += 4) {
        float v0 = vs[m * 32 + d];
        float v1 = vs[(m + 1) * 32 + d];
        float v2 = vs[(m + 2) * 32 + d];
        float v3 = vs[(m + 3) * 32 + d];
#pragma unroll
        for (int k = 0; k < 4; k++) {
            int nl = nb + k * 8;
            float4 rr = *(const float4*)(rs + nl * 256 + m);
            acc[k] += rr.x * v0 + rr.y * v1 + rr.z * v2 + rr.w * v3;
        }
    }
#pragma unroll
    for (int k = 0; k < 4; k++) {
        int nl = nb + k * 8;
        S_hout[(size_t)(b * 1024 + n0 + nl) * 256 + h * 32 + d] = acc[k];
    }
}

// ---------------- output projection + NCHW transpose ----------------
__global__ __launch_bounds__(256) void k_out(const float* __restrict__ Wp, const float* __restrict__ bp,
                                             float* __restrict__ out) {
    const int b = blockIdx.x;
    const int n0 = blockIdx.y * 32;
    extern __shared__ float sm2[];
    float* hs = sm2;
    for (int idx = threadIdx.x; idx < 8192; idx += 256) {
        int nl = idx >> 8, cp = idx & 255;
        hs[cp * 36 + nl] = S_hout[(size_t)(b * 1024 + n0 + nl) * 256 + cp];
    }
    __syncthreads();
    int c = threadIdx.x;
    float acc[32];
#pragma unroll
    for (int i = 0; i < 32; i++) acc[i] = 0.f;
    const float* wrow = Wp + c * 256;
    for (int cp = 0; cp < 256; cp++) {
        float w = __ldg(wrow + cp);
        const float4* h4 = (const float4*)(hs + cp * 36);
#pragma unroll
        for (int i4 = 0; i4 < 8; i4++) {
            float4 hh = h4[i4];
            acc[i4 * 4 + 0] += hh.x * w;
            acc[i4 * 4 + 1] += hh.y * w;
            acc[i4 * 4 + 2] += hh.z * w;
            acc[i4 * 4 + 3] += hh.w * w;
        }
    }
    float bpc = bp[c];
    __syncthreads();
    float* os = sm2;
#pragma unroll
    for (int i = 0; i < 32; i++) os[c * 36 + i] = acc[i] + bpc;
    __syncthreads();
    for (int idx = threadIdx.x; idx < 8192; idx += 256) {
        int c2 = idx >> 5, i2 = idx & 31;
        out[((size_t)b * 256 + c2) * 1024 + n0 + i2] = os[c2 * 36 + i2];
    }
}

// ---------------- host launcher ----------------
extern "C" void kernel_launch(void* const* d_in, const int* in_sizes, int n_in,
                              void* d_out, int out_size) {
    const float* q     = (const float*)d_in[0];
    const float* kv    = (const float*)d_in[1];
    const float* Wq    = (const float*)d_in[2];
    const float* Wkv   = (const float*)d_in[3];
    const float* Wp    = (const float*)d_in[4];
    const float* bp    = (const float*)d_in[5];
    const float* rpb   = (const float*)d_in[6];
    const float* W_exp = (const float*)d_in[7];
    const float* g1    = (const float*)d_in[8];
    const float* b1    = (const float*)d_in[9];
    const float* W_dw  = (const float*)d_in[10];
    const float* g2    = (const float*)d_in[11];
    const float* b2    = (const float*)d_in[12];
    const float* W_red = (const float*)d_in[13];
    const float* g3    = (const float*)d_in[14];
    const float* b3    = (const float*)d_in[15];
    float* out = (float*)d_out;

    cudaFuncSetAttribute(k_dla0, cudaFuncAttributeMaxDynamicSharedMemorySize, 24 * 360 * 4);
    cudaFuncSetAttribute(k_av, cudaFuncAttributeMaxDynamicSharedMemorySize, 65536);
    cudaFuncSetAttribute(k_out, cudaFuncAttributeMaxDynamicSharedMemorySize, 256 * 36 * 4);

    k_all_proj<<<dim3(16, 48), 256>>>(q, Wq, kv, Wkv);          // 0
    k_attn<<<dim3(128, 16), 256>>>(rpb);                        // 1
    k_gram<<<dim3(16, 32), 256>>>();                            // 2
    k_dla0<<<dim3(8, 128, 16), 256, 24 * 360 * 4>>>(W_exp, g1, b1, W_dw);  // 3 <- ncu capture slot
    k_red<<<dim3(16, 128), 256>>>(g2, b2, W_red);               // 4
    k_av<<<dim3(128, 32), 256, 65536>>>(g3, b3);                // 5
    k_out<<<dim3(16, 32), 256, 256 * 36 * 4>>>(Wp, bp, out);    // 6
}

// round 17
// speedup vs baseline: 1.5560x; 1.0508x over previous
#include <cuda_runtime.h>
#include <math.h>

#define B_   16
#define C_   256
#define NH_  8
#define HD_  32
#define N_   1024
#define M_   256
#define HID_ 24
#define EPS_ 1e-5f

// ---------------- scratch ----------------
__device__ float S_q[B_ * NH_ * N_ * HD_];
__device__ float S_k[B_ * NH_ * M_ * HD_];
__device__ float S_v[B_ * NH_ * M_ * HD_];
__device__ float S_attn[B_ * NH_ * N_ * M_];   // 134 MB
__device__ float S_y[B_ * HID_ * N_ * M_];     // 403 MB
__device__ float S_r[B_ * NH_ * N_ * M_];      // 134 MB
__device__ float S_hout[B_ * N_ * C_];
__device__ float S_gram[B_ * 36];
__device__ float S_stats2[B_ * 3 * 2];
__device__ float S_stats3[B_ * 2];

__device__ __forceinline__ float wred(float v) {
#pragma unroll
    for (int o = 16; o; o >>= 1) v += __shfl_xor_sync(0xffffffffu, v, o);
    return v;
}
__device__ __forceinline__ float tanh_fast(float x) {
    float y;
    asm("tanh.approx.f32 %0, %1;" : "=f"(y) : "f"(x));
    return y;
}
__device__ __forceinline__ float fswish(float x) {
    return 0.5f * x * (1.f + tanh_fast(0.5f * x));
}

// ---------------- fused projections (q + kv) + scratch zeroing ----------------
__global__ __launch_bounds__(256) void k_all_proj(
    const float* __restrict__ q, const float* __restrict__ Wq,
    const float* __restrict__ kv, const float* __restrict__ Wkv) {
    __shared__ float sbuf[8192];
    const int b = blockIdx.x;
    const int y = blockIdx.y;
    const int t = threadIdx.x;
    if (b == 0 && y == 0) {
        for (int i = t; i < 576; i += 256) S_gram[i] = 0.f;
        if (t < 96) S_stats2[t] = 0.f;
        if (t < 32) S_stats3[t] = 0.f;
    }
    if (y < 32) {
        const int n0 = y * 32;
        for (int idx = t; idx < 2048; idx += 256) {
            int c = idx >> 3, i4 = idx & 7;
            ((float4*)sbuf)[idx] = ((const float4*)(q + (b * 256 + c) * 1024 + n0))[i4];
        }
        __syncthreads();
        float acc[32];
#pragma unroll
        for (int i = 0; i < 32; i++) acc[i] = 0.f;
        const float* wrow = Wq + t * 256;
        for (int c = 0; c < 256; c++) {
            float w = __ldg(wrow + c);
            const float4* q4 = (const float4*)(sbuf + c * 32);
#pragma unroll
            for (int i4 = 0; i4 < 8; i4++) {
                float4 qq = q4[i4];
                acc[i4 * 4 + 0] += qq.x * w;
                acc[i4 * 4 + 1] += qq.y * w;
                acc[i4 * 4 + 2] += qq.z * w;
                acc[i4 * 4 + 3] += qq.w * w;
            }
        }
        int h = t >> 5, d = t & 31;
#pragma unroll
        for (int i = 0; i < 32; i++)
            S_q[((b * 8 + h) * 1024 + n0 + i) * 32 + d] = acc[i];
    } else {
        const int m0 = (y - 32) * 16;
        for (int idx = t; idx < 4096; idx += 256) {
            int c = idx >> 4, i = idx & 15;
            sbuf[c * 16 + i] = kv[(b * 256 + c) * 256 + m0 + i];
        }
        __syncthreads();
        for (int jj = 0; jj < 2; jj++) {
            int j = t + jj * 256;
            float acc[16];
#pragma unroll
            for (int i = 0; i < 16; i++) acc[i] = 0.f;
            const float* wrow = Wkv + j * 256;
            for (int c = 0; c < 256; c++) {
                float w = __ldg(wrow + c);
                const float4* k4 = (const float4*)(sbuf + c * 16);
#pragma unroll
                for (int i4 = 0; i4 < 4; i4++) {
                    float4 kk = k4[i4];
                    acc[i4 * 4 + 0] += kk.x * w;
                    acc[i4 * 4 + 1] += kk.y * w;
                    acc[i4 * 4 + 2] += kk.z * w;
                    acc[i4 * 4 + 3] += kk.w * w;
                }
            }
            float* dst = (j < 256) ? S_k : S_v;
            int hd = j & 255;
            int h = hd >> 5, d = hd & 31;
#pragma unroll
            for (int i = 0; i < 16; i++)
                dst[((b * 8 + h) * 256 + m0 + i) * 32 + d] = acc[i];
        }
    }
}

// ---------------- attention: register-tiled QK^T + softmax (fp32) ----------------
__global__ __launch_bounds__(256) void k_attn(const float* __restrict__ rpb) {
    const int bh = blockIdx.x;
    const int n0 = blockIdx.y * 64;
    __shared__ float Qs[32 * 68];
    __shared__ float Ks[32 * 260];
    const int t = threadIdx.x;
    {
        const int d = t & 31, g = t >> 5;
        const float* qsrc = S_q + (size_t)(bh * 1024 + n0) * 32 + d;
#pragma unroll
        for (int i = 0; i < 8; i++)
            Qs[d * 68 + g * 8 + i] = qsrc[(g * 8 + i) * 32];
        const float* ksrc = S_k + (size_t)bh * 8192 + d;
#pragma unroll
        for (int i = 0; i < 32; i++)
            Ks[d * 260 + g * 32 + i] = ksrc[(g * 32 + i) * 32];
    }
    __syncthreads();
    const int mg = t & 31;
    const int ng = t >> 5;
    float acc[8][8];
#pragma unroll
    for (int i = 0; i < 8; i++)
#pragma unroll
        for (int j = 0; j < 8; j++) acc[i][j] = 0.f;
#pragma unroll 4
    for (int k = 0; k < 32; k++) {
        float4 q0 = *(const float4*)&Qs[k * 68 + ng * 8];
        float4 q1 = *(const float4*)&Qs[k * 68 + ng * 8 + 4];
        float4 k0 = *(const float4*)&Ks[k * 260 + mg * 8];
        float4 k1 = *(const float4*)&Ks[k * 260 + mg * 8 + 4];
        float qv[8] = {q0.x, q0.y, q0.z, q0.w, q1.x, q1.y, q1.z, q1.w};
        float kw[8] = {k0.x, k0.y, k0.z, k0.w, k1.x, k1.y, k1.z, k1.w};
#pragma unroll
        for (int i = 0; i < 8; i++)
#pragma unroll
            for (int j = 0; j < 8; j++) acc[i][j] += qv[i] * kw[j];
    }
    const float scale = 0.17677669529663689f;
#pragma unroll
    for (int i = 0; i < 8; i++) {
        const int n = n0 + ng * 8 + i;
        const float* rp = rpb + (size_t)n * 256 + mg * 8;
        float4 r0 = *(const float4*)rp;
        float4 r1 = *(const float4*)(rp + 4);
        float rb[8] = {r0.x, r0.y, r0.z, r0.w, r1.x, r1.y, r1.z, r1.w};
        float mx = -1e30f;
#pragma unroll
        for (int j = 0; j < 8; j++) {
            acc[i][j] = acc[i][j] * scale + rb[j];
            mx = fmaxf(mx, acc[i][j]);
        }
#pragma unroll
        for (int o = 16; o; o >>= 1) mx = fmaxf(mx, __shfl_xor_sync(0xffffffffu, mx, o));
        float s = 0.f;
#pragma unroll
        for (int j = 0; j < 8; j++) {
            float e = __expf(acc[i][j] - mx);
            acc[i][j] = e;
            s += e;
        }
        s = wred(s);
        float inv = __fdividef(1.f, s);
        float* dst = S_attn + (size_t)(bh * 1024 + n) * 256 + mg * 8;
        float4 o0 = make_float4(acc[i][0] * inv, acc[i][1] * inv, acc[i][2] * inv, acc[i][3] * inv);
        float4 o1 = make_float4(acc[i][4] * inv, acc[i][5] * inv, acc[i][6] * inv, acc[i][7] * inv);
        *(float4*)dst = o0;
        *(float4*)(dst + 4) = o1;
    }
}

// ---------------- head Gram matrix (float4 quads) ----------------
__global__ __launch_bounds__(256) void k_gram() {
    const int b = blockIdx.x;
    const int base = blockIdx.y * 2048;   // quad index; grid.y = 32
    __shared__ float gs[36];
    const int t = threadIdx.x;
    if (t < 36) gs[t] = 0.f;
    __syncthreads();
    float g[36];
#pragma unroll
    for (int c = 0; c < 36; c++) g[c] = 0.f;
    const float4* A = (const float4*)(S_attn + (size_t)b * 2097152);
#pragma unroll 1
    for (int k = 0; k < 8; k++) {
        int qd = base + k * 256 + t;
        float4 a[8];
#pragma unroll
        for (int h = 0; h < 8; h++) a[h] = A[h * 65536 + qd];
        int c = 0;
#pragma unroll
        for (int i = 0; i < 8; i++)
#pragma unroll
            for (int j = i; j < 8; j++) {
                g[c] += a[i].x * a[j].x + a[i].y * a[j].y
                      + a[i].z * a[j].z + a[i].w * a[j].w;
                c++;
            }
    }
#pragma unroll
    for (int c = 0; c < 36; c++) {
        g[c] = wred(g[c]);
        if ((t & 31) == 0) atomicAdd(&gs[c], g[c]);
    }
    __syncthreads();
    if (t < 36) atomicAdd(&S_gram[b * 36 + t], gs[t]);
}

// ---------------- DLA pass 0: stats-from-gram + expand+GN1+swish+dw3x3 ----------------
// xact layout: 24 channels x 10 rows x stride 36 (halo cols 0..33 = global m0-1..m0+32)
__global__ __launch_bounds__(256, 4) void k_dla0(
    const float* __restrict__ W_exp, const float* __restrict__ g1,
    const float* __restrict__ b1, const float* __restrict__ W_dw) {
    const int m0 = blockIdx.x * 32;
    const int n0 = blockIdx.y * 8;      // 8-row core tile
    const int b = blockIdx.z;
    extern __shared__ float xact[];     // 24 * 360 floats = 34560 B
    __shared__ float we[192], wd[216];
    __shared__ float g1s[24], b1s[24];
    __shared__ float Gs[36];
    __shared__ float osum[24], osq[24];
    __shared__ float mu1[3], rs1[3];
    __shared__ float red[6];
    const int t = threadIdx.x;
    if (t < 192) we[t] = W_exp[t];
    if (t < 216) wd[t] = W_dw[t];
    if (t < 24) { g1s[t] = g1[t]; b1s[t] = b1[t]; }
    if (t < 36) Gs[t] = S_gram[b * 36 + t];
    if (t < 6) red[t] = 0.f;
    __syncthreads();
    // GN1 stats analytically from Gram
    if (t < 24) {
        const int o = t;
        float wo[8];
#pragma unroll
        for (int h = 0; h < 8; h++) wo[h] = we[o * 8 + h];
        float sw = 0.f;
#pragma unroll
        for (int h = 0; h < 8; h++) sw += wo[h];
        float sxx = 0.f;
#pragma unroll
        for (int i = 0; i < 8; i++)
#pragma unroll
            for (int j = 0; j < 8; j++) {
                int a = i < j ? i : j, bb = i < j ? j : i;
                sxx += wo[i] * wo[j] * Gs[8 * a - a * (a - 1) / 2 + (bb - a)];
            }
        osum[t] = sw;
        osq[t] = sxx;
    }
    __syncthreads();
    if (t < 3) {
        float sw = 0.f, sxx = 0.f;
#pragma unroll
        for (int k = 0; k < 8; k++) { sw += osum[t * 8 + k]; sxx += osq[t * 8 + k]; }
        float m = sw * (1024.f / 2097152.f);
        mu1[t] = m;
        rs1[t] = rsqrtf(sxx * (1.f / 2097152.f) - m * m + EPS_);
    }
    __syncthreads();

    // Phase 1: activated expand tile with halo, 2-pixel pairs, float2 STS
    const float* Ab = S_attn + (size_t)b * 2097152;
#pragma unroll 1
    for (int pp = t; pp < 170; pp += 256) {
        int row = pp / 17;
        int jp = (pp - row * 17) * 2;
        int gi = n0 - 1 + row;
        int gj = m0 - 1 + jp;
        int sidx = row * 36 + jp;
        bool vrow = (unsigned)gi < 1024u;
        bool v0 = vrow && ((unsigned)gj < 256u);
        bool v1 = vrow && ((unsigned)(gj + 1) < 256u);
        const float* A = Ab + gi * 256 + gj;
        float a0[8], a1[8];
#pragma unroll
        for (int h = 0; h < 8; h++) {
            a0[h] = v0 ? A[h * 262144] : 0.f;
            a1[h] = v1 ? A[h * 262144 + 1] : 0.f;
        }
#pragma unroll
        for (int o = 0; o < 24; o++) {
            float x0 = 0.f, x1 = 0.f;
#pragma unroll
            for (int h = 0; h < 8; h++) {
                float w = we[o * 8 + h];
                x0 += w * a0[h];
                x1 += w * a1[h];
            }
            int g = o >> 3;
            float S = rs1[g] * g1s[o];
            float T = b1s[o] - mu1[g] * S;
            x0 = x0 * S + T;
            x1 = x1 * S + T;
            x0 = v0 ? fswish(x0) : 0.f;
            x1 = v1 ? fswish(x1) : 0.f;
            *(float2*)&xact[o * 360 + sidx] = make_float2(x0, x1);
        }
    }
    __syncthreads();

    // Phase 2: dwconv over 8x32 core, 2-pixel pairs, float2 smem loads
    {
        const int half = t >> 7;
        const int pl = t & 127;
        const int i = pl >> 4;
        const int p = pl & 15;
        const int ob = half * 12;
        size_t gp = (size_t)(n0 + i) * 256 + (m0 + 2 * p);
        float sA = 0, qA = 0, sB = 0, qB = 0;
#pragma unroll 4
        for (int c = 0; c < 12; c++) {
            const int o = ob + c;
            const float* xb = xact + o * 360 + i * 36 + 2 * p;
            const float* w = wd + o * 9;
            float2 a0 = *(const float2*)(xb);
            float2 b0 = *(const float2*)(xb + 2);
            float2 a1 = *(const float2*)(xb + 36);
            float2 b1 = *(const float2*)(xb + 38);
            float2 a2 = *(const float2*)(xb + 72);
            float2 b2 = *(const float2*)(xb + 74);
            float y0 = w[0] * a0.x + w[1] * a0.y + w[2] * b0.x
                     + w[3] * a1.x + w[4] * a1.y + w[5] * b1.x
                     + w[6] * a2.x + w[7] * a2.y + w[8] * b2.x;
            float y1 = w[0] * a0.y + w[1] * b0.x + w[2] * b0.y
                     + w[3] * a1.y + w[4] * b1.x + w[5] * b1.y
                     + w[6] * a2.y + w[7] * b2.x + w[8] * b2.y;
            *(float2*)&S_y[((size_t)(b * 24 + o)) * 262144 + gp] = make_float2(y0, y1);
            float sv = y0 + y1, qv = y0 * y0 + y1 * y1;
            bool first = (half == 0) ? (c < 8) : (c < 4);
            if (first) { sA += sv; qA += qv; }
            else       { sB += sv; qB += qv; }
        }
        sA = wred(sA); qA = wred(qA); sB = wred(sB); qB = wred(qB);
        if ((t & 31) == 0) {
            if (half == 0) {
                atomicAdd(&red[0], sA); atomicAdd(&red[1], qA);
                atomicAdd(&red[2], sB); atomicAdd(&red[3], qB);
            } else {
                atomicAdd(&red[2], sA); atomicAdd(&red[3], qA);
                atomicAdd(&red[4], sB); atomicAdd(&red[5], qB);
            }
        }
    }
    __syncthreads();
    if (t < 6) atomicAdd(&S_stats2[b * 6 + t], red[t]);
}

// ---------------- DLA pass 1: GN2->swish->1x1 reduce, 4-pixel quads (float4 I/O) ----------------
__global__ __launch_bounds__(256) void k_red(
    const float* __restrict__ g2, const float* __restrict__ b2,
    const float* __restrict__ W_red) {
    const int b = blockIdx.x;
    const int q0 = blockIdx.y * 1024;   // quad index; grid.y = 64
    __shared__ float wrd[192], g2s[24], b2s[24];
    __shared__ float mu2[3], rs2[3];
    __shared__ float red[2];
    const int t = threadIdx.x;
    if (t < 192) wrd[t] = W_red[t];
    if (t < 24) { g2s[t] = g2[t]; b2s[t] = b2[t]; }
    if (t < 3) {
        const float cnt = 2097152.f;
        float s = S_stats2[b * 6 + 2 * t], qq = S_stats2[b * 6 + 2 * t + 1];
        float m = s / cnt;
        mu2[t] = m;
        rs2[t] = rsqrtf(qq / cnt - m * m + EPS_);
    }
    if (t < 2) red[t] = 0.f;
    __syncthreads();
    float s3 = 0, q3 = 0;
    const float4* Y = (const float4*)(S_y + (size_t)b * 24 * 262144);
    float4* R = (float4*)(S_r + (size_t)b * 8 * 262144);
#pragma unroll 1
    for (int k = 0; k < 4; k++) {
        int qd = q0 + k * 256 + t;
        float r0[8], r1[8], r2[8], r3[8];
#pragma unroll
        for (int h = 0; h < 8; h++) { r0[h] = 0.f; r1[h] = 0.f; r2[h] = 0.f; r3[h] = 0.f; }
#pragma unroll
        for (int o = 0; o < 24; o++) {
            float4 yf = Y[(size_t)o * 65536 + qd];
            int g = o >> 3;
            float S = rs2[g] * g2s[o];
            float T = b2s[o] - mu2[g] * S;
            float z0 = fswish(yf.x * S + T);
            float z1 = fswish(yf.y * S + T);
            float z2 = fswish(yf.z * S + T);
            float z3 = fswish(yf.w * S + T);
#pragma unroll
            for (int h = 0; h < 8; h++) {
                float w = wrd[h * 24 + o];
                r0[h] += w * z0;
                r1[h] += w * z1;
                r2[h] += w * z2;
                r3[h] += w * z3;
            }
        }
#pragma unroll
        for (int h = 0; h < 8; h++) {
            R[(size_t)h * 65536 + qd] = make_float4(r0[h], r1[h], r2[h], r3[h]);
            s3 += r0[h] + r1[h] + r2[h] + r3[h];
            q3 += r0[h] * r0[h] + r1[h] * r1[h] + r2[h] * r2[h] + r3[h] * r3[h];
        }
    }
    s3 = wred(s3); q3 = wred(q3);
    if ((t & 31) == 0) { atomicAdd(&red[0], s3); atomicAdd(&red[1], q3); }
    __syncthreads();
    if (t < 2) atomicAdd(&S_stats3[b * 2 + t], red[t]);
}

// ---------------- AV product (GN3 on the fly), transposed V in smem ----------------
__global__ __launch_bounds__(256) void k_av(const float* __restrict__ g3, const float* __restrict__ b3) {
    const int bh = blockIdx.x;
    const int n0 = blockIdx.y * 32;
    const int b = bh >> 3, h = bh & 7;
    extern __shared__ float sm[];
    float* vt = sm;            // 32 * 260 = 8320 floats (V transposed [d][m])
    float* rs = sm + 8320;     // 8192 floats
    __shared__ float params[2];
    if (threadIdx.x == 0) {
        const float cnt = 2097152.f;
        float s = S_stats3[b * 2], qq = S_stats3[b * 2 + 1];
        float m = s / cnt;
        float rstd = rsqrtf(qq / cnt - m * m + EPS_);
        float gh = g3[h];
        params[0] = rstd * gh;
        params[1] = b3[h] - m * rstd * gh;
    }
    __syncthreads();
    float scl = params[0], sft = params[1];
    for (int idx = threadIdx.x; idx < 8192; idx += 256) {
        int m = idx >> 5, d = idx & 31;
        vt[d * 260 + m] = S_v[(size_t)bh * 8192 + idx];
    }
    const float* Rg = S_r + (size_t)(bh * 1024 + n0) * 256;
    for (int idx = threadIdx.x; idx < 8192; idx += 256)
        rs[idx] = Rg[idx] * scl + sft;
    __syncthreads();
    const int d = threadIdx.x & 31, nb = threadIdx.x >> 5;
    float acc[4];
#pragma unroll
    for (int k = 0; k < 4; k++) acc[k] = 0.f;
    const float* vrow = vt + d * 260;
    for (int m = 0; m < 256; m += 4) {
        float4 v4 = *(const float4*)(vrow + m);
#pragma unroll
        for (int k = 0; k < 4; k++) {
            int nl = nb + k * 8;
            float4 rr = *(const float4*)(rs + nl * 256 + m);
            acc[k] += rr.x * v4.x + rr.y * v4.y + rr.z * v4.z + rr.w * v4.w;
        }
    }
#pragma unroll
    for (int k = 0; k < 4; k++) {
        int nl = nb + k * 8;
        S_hout[(size_t)(b * 1024 + n0 + nl) * 256 + h * 32 + d] = acc[k];
    }
}

// ---------------- output projection + NCHW transpose ----------------
__global__ __launch_bounds__(256) void k_out(const float* __restrict__ Wp, const float* __restrict__ bp,
                                             float* __restrict__ out) {
    const int b = blockIdx.x;
    const int n0 = blockIdx.y * 32;
    extern __shared__ float sm2[];
    float* hs = sm2;
    for (int idx = threadIdx.x; idx < 8192; idx += 256) {
        int nl = idx >> 8, cp = idx & 255;
        hs[cp * 36 + nl] = S_hout[(size_t)(b * 1024 + n0 + nl) * 256 + cp];
    }
    __syncthreads();
    int c = threadIdx.x;
    float acc[32];
#pragma unroll
    for (int i = 0; i < 32; i++) acc[i] = 0.f;
    const float* wrow = Wp + c * 256;
    for (int cp = 0; cp < 256; cp++) {
        float w = __ldg(wrow + cp);
        const float4* h4 = (const float4*)(hs + cp * 36);
#pragma unroll
        for (int i4 = 0; i4 < 8; i4++) {
            float4 hh = h4[i4];
            acc[i4 * 4 + 0] += hh.x * w;
            acc[i4 * 4 + 1] += hh.y * w;
            acc[i4 * 4 + 2] += hh.z * w;
            acc[i4 * 4 + 3] += hh.w * w;
        }
    }
    float bpc = bp[c];
    __syncthreads();
    float* os = sm2;
#pragma unroll
    for (int i = 0; i < 32; i++) os[c * 36 + i] = acc[i] + bpc;
    __syncthreads();
    for (int idx = threadIdx.x; idx < 8192; idx += 256) {
        int c2 = idx >> 5, i2 = idx & 31;
        out[((size_t)b * 256 + c2) * 1024 + n0 + i2] = os[c2 * 36 + i2];
    }
}

// ---------------- host launcher ----------------
extern "C" void kernel_launch(void* const* d_in, const int* in_sizes, int n_in,
                              void* d_out, int out_size) {
    const float* q     = (const float*)d_in[0];
    const float* kv    = (const float*)d_in[1];
    const float* Wq    = (const float*)d_in[2];
    const float* Wkv   = (const float*)d_in[3];
    const float* Wp    = (const float*)d_in[4];
    const float* bp    = (const float*)d_in[5];
    const float* rpb   = (const float*)d_in[6];
    const float* W_exp = (const float*)d_in[7];
    const float* g1    = (const float*)d_in[8];
    const float* b1    = (const float*)d_in[9];
    const float* W_dw  = (const float*)d_in[10];
    const float* g2    = (const float*)d_in[11];
    const float* b2    = (const float*)d_in[12];
    const float* W_red = (const float*)d_in[13];
    const float* g3    = (const float*)d_in[14];
    const float* b3    = (const float*)d_in[15];
    float* out = (float*)d_out;

    cudaFuncSetAttribute(k_dla0, cudaFuncAttributeMaxDynamicSharedMemorySize, 24 * 360 * 4);
    cudaFuncSetAttribute(k_av, cudaFuncAttributeMaxDynamicSharedMemorySize, (8320 + 8192) * 4);
    cudaFuncSetAttribute(k_out, cudaFuncAttributeMaxDynamicSharedMemorySize, 256 * 36 * 4);

    k_all_proj<<<dim3(16, 48), 256>>>(q, Wq, kv, Wkv);          // 0
    k_attn<<<dim3(128, 16), 256>>>(rpb);                        // 1
    k_gram<<<dim3(16, 32), 256>>>();                            // 2
    k_dla0<<<dim3(8, 128, 16), 256, 24 * 360 * 4>>>(W_exp, g1, b1, W_dw);  // 3 <- ncu capture slot
    k_red<<<dim3(16, 64), 256>>>(g2, b2, W_red);                // 4
    k_av<<<dim3(128, 32), 256, (8320 + 8192) * 4>>>(g3, b3);    // 5
    k_out<<<dim3(16, 32), 256, 256 * 36 * 4>>>(Wp, bp, out);    // 6
}